// round 2
// baseline (speedup 1.0000x reference)
#include <cuda_runtime.h>
#include <cstdint>

// ---------------------------------------------------------------------------
// TensorNet interaction.
//   msg[n] = (component tensors of n) * (per-node scalar sums of edge MLP),
//   so the graph part is a scatter-add of 96 edge-MLP outputs into acc[n][96].
//
// R2: edge MLP processes TWO edges per thread with packed fma.rn.f32x2
//     (FFMA2), weights duplicated as (w,w) pairs in SMEM -> FMA issue count
//     halves vs scalar FFMA.
// ---------------------------------------------------------------------------

#define MAXN 50000
#define PI_F 3.14159265358979323846f
#define CUTOFF_F 5.0f
#define TPB 128

typedef unsigned long long ull;

__device__ float g_acc[(size_t)MAXN * 96];

// ---- packed f32x2 helpers --------------------------------------------------
__device__ __forceinline__ ull fma2(ull a, ull b, ull c) {
    ull d;
    asm("fma.rn.f32x2 %0, %1, %2, %3;" : "=l"(d) : "l"(a), "l"(b), "l"(c));
    return d;
}
__device__ __forceinline__ ull mul2(ull a, ull b) {
    ull d;
    asm("mul.rn.f32x2 %0, %1, %2;" : "=l"(d) : "l"(a), "l"(b));
    return d;
}
__device__ __forceinline__ ull pack2(float lo, float hi) {
    ull d;
    asm("mov.b64 %0, {%1, %2};" : "=l"(d) : "f"(lo), "f"(hi));
    return d;
}
__device__ __forceinline__ void unpack2(ull v, float& lo, float& hi) {
    asm("mov.b64 {%0, %1}, %2;" : "=f"(lo), "=f"(hi) : "l"(v));
}

__device__ __forceinline__ float silu_f(float v) {
    return v * __fdividef(1.0f, 1.0f + __expf(-v));
}
__device__ __forceinline__ ull silu2(ull v) {
    float lo, hi;
    unpack2(v, lo, hi);
    return pack2(silu_f(lo), silu_f(hi));
}

// ---------------------------------------------------------------------------
__global__ void zero_acc_kernel(int n4) {
    int i = blockIdx.x * blockDim.x + threadIdx.x;
    if (i < n4) reinterpret_cast<float4*>(g_acc)[i] = make_float4(0.f, 0.f, 0.f, 0.f);
}

// ---------------------------------------------------------------------------
// Edge MLP, two edges per thread, packed f32x2 math.
// Dynamic SMEM layout (float2 pairs, each weight duplicated (w,w)):
//   sW1 : 1024 pairs, layout [k][o]   (k in 0..31, o in 0..31)
//   sW2 : 2048 pairs, layout [k][o]   (k in 0..31, o in 0..63)
//   sW3 : 6144 pairs, layout [o][k]   (o in 0..95, k in 0..63)
//   sB1 : 32, sB2 : 64, sB3 : 96 pairs
__global__ void __launch_bounds__(TPB)
edge_mlp_kernel(const float* __restrict__ edge_attr,
                const int*   __restrict__ edge_index,
                const float* __restrict__ edge_weight,
                const float* __restrict__ W1, const float* __restrict__ b1,
                const float* __restrict__ W2, const float* __restrict__ b2,
                const float* __restrict__ W3, const float* __restrict__ b3,
                int E)
{
    extern __shared__ float2 smem2[];
    float2* sW1 = smem2;            // 1024
    float2* sW2 = sW1 + 1024;       // 2048
    float2* sW3 = sW2 + 2048;       // 6144
    float2* sB1 = sW3 + 6144;       // 32
    float2* sB2 = sB1 + 32;         // 64
    float2* sB3 = sB2 + 64;         // 96

    for (int i = threadIdx.x; i < 1024; i += TPB) {
        int k = i >> 5, o = i & 31;
        float w = W1[o * 32 + k];
        sW1[i] = make_float2(w, w);
    }
    for (int i = threadIdx.x; i < 2048; i += TPB) {
        int k = i >> 6, o = i & 63;
        float w = W2[o * 32 + k];
        sW2[i] = make_float2(w, w);
    }
    for (int i = threadIdx.x; i < 6144; i += TPB) {
        int o = i >> 6, k = i & 63;
        float w = W3[o * 64 + k];
        sW3[i] = make_float2(w, w);
    }
    if (threadIdx.x < 32) { float v = b1[threadIdx.x]; sB1[threadIdx.x] = make_float2(v, v); }
    if (threadIdx.x < 64) { float v = b2[threadIdx.x]; sB2[threadIdx.x] = make_float2(v, v); }
    if (threadIdx.x < 96) { float v = b3[threadIdx.x]; sB3[threadIdx.x] = make_float2(v, v); }
    __syncthreads();

    int gid = blockIdx.x * TPB + threadIdx.x;
    int e0 = 2 * gid;
    if (e0 >= E) return;
    bool has1 = (e0 + 1) < E;
    int e1 = has1 ? (e0 + 1) : e0;

    // ---- load & pack edge_attr rows ----
    ull x2[32];
    {
        const float4* ra = reinterpret_cast<const float4*>(edge_attr + (size_t)e0 * 32);
        const float4* rb = reinterpret_cast<const float4*>(edge_attr + (size_t)e1 * 32);
        #pragma unroll
        for (int q = 0; q < 8; q++) {
            float4 a = __ldg(ra + q);
            float4 b = __ldg(rb + q);
            x2[4*q+0] = pack2(a.x, b.x);
            x2[4*q+1] = pack2(a.y, b.y);
            x2[4*q+2] = pack2(a.z, b.z);
            x2[4*q+3] = pack2(a.w, b.w);
        }
    }

    float wA = edge_weight[e0];
    float wB = edge_weight[e1];
    float CcA = (wA < CUTOFF_F) ? 0.5f * (__cosf(wA * (PI_F / CUTOFF_F)) + 1.0f) : 0.0f;
    float CcB = (wB < CUTOFF_F) ? 0.5f * (__cosf(wB * (PI_F / CUTOFF_F)) + 1.0f) : 0.0f;
    ull cc2 = pack2(CcA, CcB);
    int dstA = edge_index[E + e0];
    int dstB = edge_index[E + e1];

    const ull* uB1 = reinterpret_cast<const ull*>(sB1);
    const ull* uB2 = reinterpret_cast<const ull*>(sB2);
    const ull* uB3 = reinterpret_cast<const ull*>(sB3);

    // ---- Layer 1: 32 -> 32 (k outer, 32 independent packed accumulators) ----
    ull acc1[32];
    #pragma unroll
    for (int o = 0; o < 32; o++) acc1[o] = uB1[o];
    #pragma unroll
    for (int k = 0; k < 32; k++) {
        ull xv = x2[k];
        const ulonglong2* wp = reinterpret_cast<const ulonglong2*>(sW1 + (k << 5));
        #pragma unroll
        for (int o2 = 0; o2 < 16; o2++) {
            ulonglong2 w = wp[o2];
            acc1[2*o2]   = fma2(w.x, xv, acc1[2*o2]);
            acc1[2*o2+1] = fma2(w.y, xv, acc1[2*o2+1]);
        }
    }
    #pragma unroll
    for (int o = 0; o < 32; o++) acc1[o] = silu2(acc1[o]);   // acc1 = h1

    // ---- Layer 2: 32 -> 64 ----
    ull acc2[64];
    #pragma unroll
    for (int o = 0; o < 64; o++) acc2[o] = uB2[o];
    #pragma unroll
    for (int k = 0; k < 32; k++) {
        ull xv = acc1[k];
        const ulonglong2* wp = reinterpret_cast<const ulonglong2*>(sW2 + (k << 6));
        #pragma unroll
        for (int o2 = 0; o2 < 32; o2++) {
            ulonglong2 w = wp[o2];
            acc2[2*o2]   = fma2(w.x, xv, acc2[2*o2]);
            acc2[2*o2+1] = fma2(w.y, xv, acc2[2*o2+1]);
        }
    }
    #pragma unroll
    for (int o = 0; o < 64; o++) acc2[o] = silu2(acc2[o]);   // acc2 = h2

    // ---- Layer 3: 64 -> 96, 12 groups of 8 outputs, rolled to save I$ ----
    float* accA = g_acc + (size_t)dstA * 96;
    float* accB = g_acc + (size_t)dstB * 96;
    #pragma unroll 1
    for (int g = 0; g < 12; g++) {
        ull t[8];
        #pragma unroll
        for (int oo = 0; oo < 8; oo++) {
            int o = g * 8 + oo;
            ull a = uB3[o];
            const ulonglong2* wp = reinterpret_cast<const ulonglong2*>(sW3 + (o << 6));
            #pragma unroll
            for (int q = 0; q < 32; q++) {
                ulonglong2 w = wp[q];
                a = fma2(w.x, acc2[2*q],   a);
                a = fma2(w.y, acc2[2*q+1], a);
            }
            t[oo] = mul2(silu2(a), cc2);
        }
        float lo[8], hi[8];
        #pragma unroll
        for (int oo = 0; oo < 8; oo++) unpack2(t[oo], lo[oo], hi[oo]);

        asm volatile("red.global.add.v4.f32 [%0], {%1, %2, %3, %4};"
                     :: "l"(accA + g * 8),     "f"(lo[0]), "f"(lo[1]), "f"(lo[2]), "f"(lo[3]) : "memory");
        asm volatile("red.global.add.v4.f32 [%0], {%1, %2, %3, %4};"
                     :: "l"(accA + g * 8 + 4), "f"(lo[4]), "f"(lo[5]), "f"(lo[6]), "f"(lo[7]) : "memory");
        if (has1) {
            asm volatile("red.global.add.v4.f32 [%0], {%1, %2, %3, %4};"
                         :: "l"(accB + g * 8),     "f"(hi[0]), "f"(hi[1]), "f"(hi[2]), "f"(hi[3]) : "memory");
            asm volatile("red.global.add.v4.f32 [%0], {%1, %2, %3, %4};"
                         :: "l"(accB + g * 8 + 4), "f"(hi[4]), "f"(hi[5]), "f"(hi[6]), "f"(hi[7]) : "memory");
        }
    }
}

// ---------------------------------------------------------------------------
// Node kernel: one warp per node, lane = unit (U=32).
#define NODE_WARPS 8
__global__ void __launch_bounds__(32 * NODE_WARPS)
node_kernel(const float* __restrict__ X,
            const float* __restrict__ Wt,
            float* __restrict__ out,
            int nNodes)
{
    __shared__ float sWt[6][32][32];            // sWt[c][k][m] = Wt[c][m][k]
    __shared__ float vst[NODE_WARPS][32][12];

    for (int i = threadIdx.x; i < 6144; i += 32 * NODE_WARPS) {
        int c = i >> 10, r = i & 1023;
        int m = r >> 5, k = r & 31;
        sWt[c][k][m] = Wt[i];
    }
    __syncthreads();

    int warpId = threadIdx.x >> 5;
    int lane   = threadIdx.x & 31;
    float (*vp)[12] = vst[warpId];

    for (int n = blockIdx.x * NODE_WARPS + warpId; n < nNodes;
         n += gridDim.x * NODE_WARPS) {

        float Xn[9];
        float nrm = 1.0f;
        #pragma unroll
        for (int t = 0; t < 9; t++) {
            float v = X[((size_t)n * 9 + t) * 32 + lane];
            Xn[t] = v; nrm += v * v;
        }
        float inv = __fdividef(1.0f, nrm);
        #pragma unroll
        for (int t = 0; t < 9; t++) Xn[t] *= inv;

        float tr3 = (Xn[0] + Xn[4] + Xn[8]) * (1.0f / 3.0f);
        float c[9];
        c[0] = tr3;
        c[1] = 0.5f * (Xn[1] - Xn[3]);
        c[2] = 0.5f * (Xn[2] - Xn[6]);
        c[3] = 0.5f * (Xn[5] - Xn[7]);
        c[4] = Xn[0] - tr3;
        c[5] = 0.5f * (Xn[1] + Xn[3]);
        c[6] = 0.5f * (Xn[2] + Xn[6]);
        c[7] = Xn[4] - tr3;
        c[8] = 0.5f * (Xn[5] + Xn[7]);

        __syncwarp();
        #pragma unroll
        for (int t = 0; t < 9; t++) vp[lane][t] = c[t];
        __syncwarp();

        float r[9] = {0,0,0,0,0,0,0,0,0};
        #pragma unroll 8
        for (int k = 0; k < 32; k++) {
            const float4* q4 = reinterpret_cast<const float4*>(&vp[k][0]);
            float4 p0 = q4[0], p1 = q4[1];
            float v8 = vp[k][8];
            float wI = sWt[0][k][lane];
            float wA = sWt[1][k][lane];
            float wS = sWt[2][k][lane];
            r[0] += wI * p0.x;
            r[1] += wA * p0.y; r[2] += wA * p0.z; r[3] += wA * p0.w;
            r[4] += wS * p1.x; r[5] += wS * p1.y; r[6] += wS * p1.z;
            r[7] += wS * p1.w; r[8] += wS * v8;
        }

        float Ip = r[0], a01 = r[1], a02 = r[2], a12 = r[3];
        float s00 = r[4], s01 = r[5], s02 = r[6], s11 = r[7], s12 = r[8];
        float s22 = -(s00 + s11);

        const float* ap = g_acc + (size_t)n * 96 + lane * 3;
        float sI = ap[0], sA = ap[1], sS = ap[2];

        float Y[9], G[9];
        Y[0] = Ip + s00;  Y[1] = a01 + s01;  Y[2] = a02 + s02;
        Y[3] = s01 - a01; Y[4] = Ip + s11;   Y[5] = a12 + s12;
        Y[6] = s02 - a02; Y[7] = s12 - a12;  Y[8] = Ip + s22;
        G[0] = Ip*sI + s00*sS;  G[1] = a01*sA + s01*sS;  G[2] = a02*sA + s02*sS;
        G[3] = s01*sS - a01*sA; G[4] = Ip*sI + s11*sS;   G[5] = a12*sA + s12*sS;
        G[6] = s02*sS - a02*sA; G[7] = s12*sS - a12*sA;  G[8] = Ip*sI + s22*sS;

        float M[9];
        #pragma unroll
        for (int i = 0; i < 3; i++)
            #pragma unroll
            for (int l = 0; l < 3; l++) {
                float a2 = 0.0f;
                #pragma unroll
                for (int j = 0; j < 3; j++)
                    a2 += Y[i*3+j] * G[j*3+l] + G[i*3+j] * Y[j*3+l];
                M[i*3+l] = a2;
            }

        float np = 1.0f;
        #pragma unroll
        for (int t = 0; t < 9; t++) np += M[t] * M[t];
        float inv2 = __fdividef(1.0f, np);
        float trm = (M[0] + M[4] + M[8]) * (1.0f / 3.0f);
        c[0] = trm * inv2;
        c[1] = 0.5f * (M[1] - M[3]) * inv2;
        c[2] = 0.5f * (M[2] - M[6]) * inv2;
        c[3] = 0.5f * (M[5] - M[7]) * inv2;
        c[4] = (M[0] - trm) * inv2;
        c[5] = 0.5f * (M[1] + M[3]) * inv2;
        c[6] = 0.5f * (M[2] + M[6]) * inv2;
        c[7] = (M[4] - trm) * inv2;
        c[8] = 0.5f * (M[5] + M[7]) * inv2;

        __syncwarp();
        #pragma unroll
        for (int t = 0; t < 9; t++) vp[lane][t] = c[t];
        __syncwarp();

        float r2[9] = {0,0,0,0,0,0,0,0,0};
        #pragma unroll 8
        for (int k = 0; k < 32; k++) {
            const float4* q4 = reinterpret_cast<const float4*>(&vp[k][0]);
            float4 p0 = q4[0], p1 = q4[1];
            float v8 = vp[k][8];
            float wI = sWt[3][k][lane];
            float wA = sWt[4][k][lane];
            float wS = sWt[5][k][lane];
            r2[0] += wI * p0.x;
            r2[1] += wA * p0.y; r2[2] += wA * p0.z; r2[3] += wA * p0.w;
            r2[4] += wS * p1.x; r2[5] += wS * p1.y; r2[6] += wS * p1.z;
            r2[7] += wS * p1.w; r2[8] += wS * v8;
        }
        __syncwarp();

        float Ip2 = r2[0], b01 = r2[1], b02 = r2[2], b12 = r2[3];
        float t00 = r2[4], t01 = r2[5], t02 = r2[6], t11 = r2[7], t12 = r2[8];
        float t22 = -(t00 + t11);

        float D[9];
        D[0] = Ip2 + t00;  D[1] = b01 + t01;  D[2] = b02 + t02;
        D[3] = t01 - b01;  D[4] = Ip2 + t11;  D[5] = b12 + t12;
        D[6] = t02 - b02;  D[7] = t12 - b12;  D[8] = Ip2 + t22;

        #pragma unroll
        for (int i = 0; i < 3; i++)
            #pragma unroll
            for (int l = 0; l < 3; l++) {
                float o = Xn[i*3+l] + D[i*3+l];
                #pragma unroll
                for (int j = 0; j < 3; j++)
                    o += D[i*3+j] * D[j*3+l];
                out[((size_t)n * 9 + (i*3+l)) * 32 + lane] = o;
            }
    }
}

// ---------------------------------------------------------------------------
extern "C" void kernel_launch(void* const* d_in, const int* in_sizes, int n_in,
                              void* d_out, int out_size)
{
    const float* X           = (const float*)d_in[0];
    const int*   edge_index  = (const int*)  d_in[1];
    const float* edge_weight = (const float*)d_in[2];
    const float* edge_attr   = (const float*)d_in[3];
    const float* W1 = (const float*)d_in[4];
    const float* b1 = (const float*)d_in[5];
    const float* W2 = (const float*)d_in[6];
    const float* b2 = (const float*)d_in[7];
    const float* W3 = (const float*)d_in[8];
    const float* b3 = (const float*)d_in[9];
    const float* Wt = (const float*)d_in[10];
    float* out = (float*)d_out;

    int N = in_sizes[0] / 288;   // X is (N,3,3,32)
    if (N > MAXN) N = MAXN;
    int E = in_sizes[2];         // edge_weight is (E,)

    int smemBytes = (1024 + 2048 + 6144 + 32 + 64 + 96) * (int)sizeof(float2);
    static bool attr_set = false;
    if (!attr_set) {
        cudaFuncSetAttribute(edge_mlp_kernel,
                             cudaFuncAttributeMaxDynamicSharedMemorySize, smemBytes);
        attr_set = true;
    }

    int n4 = N * 24;
    zero_acc_kernel<<<(n4 + 255) / 256, 256>>>(n4);

    int pairs = (E + 1) / 2;
    edge_mlp_kernel<<<(pairs + TPB - 1) / TPB, TPB, smemBytes>>>(
        edge_attr, edge_index, edge_weight, W1, b1, W2, b2, W3, b3, E);

    node_kernel<<<(N + NODE_WARPS - 1) / NODE_WARPS, 32 * NODE_WARPS>>>(
        X, Wt, out, N);
}

// round 3
// speedup vs baseline: 1.1512x; 1.1512x over previous
#include <cuda_runtime.h>
#include <cstdint>

// ---------------------------------------------------------------------------
// TensorNet interaction.
//   msg[n] = (component tensors of n) * (per-node scalar sums of edge MLP),
//   so the graph part is a scatter-add of 96 edge-MLP outputs into acc[n][96].
//
// R3: edge MLP with fma.rn.f32x2 packed along the REDUCTION (k) dimension,
//     one edge per thread. Weights used in natural row-major layout (pairs
//     along k), bias pre-packed (b,0) so the final horizontal add folds it.
//     Register peak ~130 (no spills), SMEM 38KB.
// ---------------------------------------------------------------------------

#define MAXN 50000
#define PI_F 3.14159265358979323846f
#define CUTOFF_F 5.0f
#define TPB 128

typedef unsigned long long ull;

__device__ float g_acc[(size_t)MAXN * 96];

// ---- packed f32x2 helpers --------------------------------------------------
__device__ __forceinline__ ull fma2(ull a, ull b, ull c) {
    ull d;
    asm("fma.rn.f32x2 %0, %1, %2, %3;" : "=l"(d) : "l"(a), "l"(b), "l"(c));
    return d;
}
__device__ __forceinline__ ull pack2(float lo, float hi) {
    ull d;
    asm("mov.b64 %0, {%1, %2};" : "=l"(d) : "f"(lo), "f"(hi));
    return d;
}
__device__ __forceinline__ void unpack2(ull v, float& lo, float& hi) {
    asm("mov.b64 {%0, %1}, %2;" : "=f"(lo), "=f"(hi) : "l"(v));
}
__device__ __forceinline__ float hsum2(ull v) {
    float lo, hi; unpack2(v, lo, hi); return lo + hi;
}

__device__ __forceinline__ float silu_f(float v) {
    return v * __fdividef(1.0f, 1.0f + __expf(-v));
}

// ---------------------------------------------------------------------------
__global__ void zero_acc_kernel(int n4) {
    int i = blockIdx.x * blockDim.x + threadIdx.x;
    if (i < n4) reinterpret_cast<float4*>(g_acc)[i] = make_float4(0.f, 0.f, 0.f, 0.f);
}

// ---------------------------------------------------------------------------
// Edge MLP: one edge per thread, f32x2 packed along k.
// SMEM: weights copied verbatim (row-major, k contiguous) -> reinterpret as
// ull pairs along k. Biases pre-packed as (b, 0).
__global__ void __launch_bounds__(TPB)
edge_mlp_kernel(const float* __restrict__ edge_attr,
                const int*   __restrict__ edge_index,
                const float* __restrict__ edge_weight,
                const float* __restrict__ W1, const float* __restrict__ b1,
                const float* __restrict__ W2, const float* __restrict__ b2,
                const float* __restrict__ W3, const float* __restrict__ b3,
                int E)
{
    __shared__ float sW1[1024];   // (32 out, 32 in) row-major
    __shared__ float sW2[2048];   // (64 out, 32 in)
    __shared__ float sW3[6144];   // (96 out, 64 in)
    __shared__ ull   sB1u[32], sB2u[64], sB3u[96];

    for (int i = threadIdx.x; i < 1024; i += TPB) sW1[i] = W1[i];
    for (int i = threadIdx.x; i < 2048; i += TPB) sW2[i] = W2[i];
    for (int i = threadIdx.x; i < 6144; i += TPB) sW3[i] = W3[i];
    if (threadIdx.x < 32) sB1u[threadIdx.x] = pack2(b1[threadIdx.x], 0.0f);
    if (threadIdx.x < 64) sB2u[threadIdx.x] = pack2(b2[threadIdx.x], 0.0f);
    if (threadIdx.x < 96) sB3u[threadIdx.x] = pack2(b3[threadIdx.x], 0.0f);
    __syncthreads();

    int e = blockIdx.x * TPB + threadIdx.x;
    if (e >= E) return;

    const ull* uW1 = reinterpret_cast<const ull*>(sW1);
    const ull* uW2 = reinterpret_cast<const ull*>(sW2);
    const ull* uW3 = reinterpret_cast<const ull*>(sW3);

    // ---- load edge_attr row, pack pairs along k ----
    ull xk[16];
    {
        const float4* xr = reinterpret_cast<const float4*>(edge_attr + (size_t)e * 32);
        #pragma unroll
        for (int q = 0; q < 8; q++) {
            float4 v = __ldg(xr + q);
            xk[2*q]   = pack2(v.x, v.y);
            xk[2*q+1] = pack2(v.z, v.w);
        }
    }

    float w = edge_weight[e];
    float Cc = (w < CUTOFF_F) ? 0.5f * (__cosf(w * (PI_F / CUTOFF_F)) + 1.0f) : 0.0f;
    int dst = edge_index[E + e];

    // ---- Layer 1: 32 -> 32 (16 fma2 per output, 32 independent chains) ----
    float h1s[32];
    #pragma unroll
    for (int o = 0; o < 32; o++) {
        ull a = sB1u[o];
        const ulonglong2* wr = reinterpret_cast<const ulonglong2*>(uW1 + o * 16);
        #pragma unroll
        for (int q = 0; q < 8; q++) {
            ulonglong2 wv = wr[q];
            a = fma2(wv.x, xk[2*q],   a);
            a = fma2(wv.y, xk[2*q+1], a);
        }
        h1s[o] = silu_f(hsum2(a));
    }
    ull h1k[16];
    #pragma unroll
    for (int q = 0; q < 16; q++) h1k[q] = pack2(h1s[2*q], h1s[2*q+1]);

    // ---- Layer 2: 32 -> 64 ----
    float h2s[64];
    #pragma unroll
    for (int o = 0; o < 64; o++) {
        ull a = sB2u[o];
        const ulonglong2* wr = reinterpret_cast<const ulonglong2*>(uW2 + o * 16);
        #pragma unroll
        for (int q = 0; q < 8; q++) {
            ulonglong2 wv = wr[q];
            a = fma2(wv.x, h1k[2*q],   a);
            a = fma2(wv.y, h1k[2*q+1], a);
        }
        h2s[o] = silu_f(hsum2(a));
    }
    ull h2k[32];
    #pragma unroll
    for (int q = 0; q < 32; q++) h2k[q] = pack2(h2s[2*q], h2s[2*q+1]);

    // ---- Layer 3: 64 -> 96, rolled groups of 8 outputs (I$ discipline) ----
    float* nodeacc = g_acc + (size_t)dst * 96;
    #pragma unroll 1
    for (int g = 0; g < 12; g++) {
        ull acc[8];
        #pragma unroll
        for (int oo = 0; oo < 8; oo++) acc[oo] = sB3u[g * 8 + oo];
        const ulonglong2* wg =
            reinterpret_cast<const ulonglong2*>(uW3 + (size_t)(g * 8) * 32);
        #pragma unroll
        for (int oo = 0; oo < 8; oo++) {
            const ulonglong2* wr = wg + oo * 16;
            #pragma unroll
            for (int q = 0; q < 16; q++) {
                ulonglong2 wv = wr[q];
                acc[oo] = fma2(wv.x, h2k[2*q],   acc[oo]);
                acc[oo] = fma2(wv.y, h2k[2*q+1], acc[oo]);
            }
        }
        float t[8];
        #pragma unroll
        for (int oo = 0; oo < 8; oo++) t[oo] = silu_f(hsum2(acc[oo])) * Cc;

        asm volatile("red.global.add.v4.f32 [%0], {%1, %2, %3, %4};"
                     :: "l"(nodeacc + g * 8),
                        "f"(t[0]), "f"(t[1]), "f"(t[2]), "f"(t[3]) : "memory");
        asm volatile("red.global.add.v4.f32 [%0], {%1, %2, %3, %4};"
                     :: "l"(nodeacc + g * 8 + 4),
                        "f"(t[4]), "f"(t[5]), "f"(t[6]), "f"(t[7]) : "memory");
    }
}

// ---------------------------------------------------------------------------
// Node kernel: one warp per node, lane = unit (U=32).
#define NODE_WARPS 8
__global__ void __launch_bounds__(32 * NODE_WARPS)
node_kernel(const float* __restrict__ X,
            const float* __restrict__ Wt,
            float* __restrict__ out,
            int nNodes)
{
    __shared__ float sWt[6][32][32];            // sWt[c][k][m] = Wt[c][m][k]
    __shared__ float vst[NODE_WARPS][32][12];

    for (int i = threadIdx.x; i < 6144; i += 32 * NODE_WARPS) {
        int c = i >> 10, r = i & 1023;
        int m = r >> 5, k = r & 31;
        sWt[c][k][m] = Wt[i];
    }
    __syncthreads();

    int warpId = threadIdx.x >> 5;
    int lane   = threadIdx.x & 31;
    float (*vp)[12] = vst[warpId];

    for (int n = blockIdx.x * NODE_WARPS + warpId; n < nNodes;
         n += gridDim.x * NODE_WARPS) {

        float Xn[9];
        float nrm = 1.0f;
        #pragma unroll
        for (int t = 0; t < 9; t++) {
            float v = X[((size_t)n * 9 + t) * 32 + lane];
            Xn[t] = v; nrm += v * v;
        }
        float inv = __fdividef(1.0f, nrm);
        #pragma unroll
        for (int t = 0; t < 9; t++) Xn[t] *= inv;

        float tr3 = (Xn[0] + Xn[4] + Xn[8]) * (1.0f / 3.0f);
        float c[9];
        c[0] = tr3;
        c[1] = 0.5f * (Xn[1] - Xn[3]);
        c[2] = 0.5f * (Xn[2] - Xn[6]);
        c[3] = 0.5f * (Xn[5] - Xn[7]);
        c[4] = Xn[0] - tr3;
        c[5] = 0.5f * (Xn[1] + Xn[3]);
        c[6] = 0.5f * (Xn[2] + Xn[6]);
        c[7] = Xn[4] - tr3;
        c[8] = 0.5f * (Xn[5] + Xn[7]);

        __syncwarp();
        #pragma unroll
        for (int t = 0; t < 9; t++) vp[lane][t] = c[t];
        __syncwarp();

        float r[9] = {0,0,0,0,0,0,0,0,0};
        #pragma unroll 8
        for (int k = 0; k < 32; k++) {
            const float4* q4 = reinterpret_cast<const float4*>(&vp[k][0]);
            float4 p0 = q4[0], p1 = q4[1];
            float v8 = vp[k][8];
            float wI = sWt[0][k][lane];
            float wA = sWt[1][k][lane];
            float wS = sWt[2][k][lane];
            r[0] += wI * p0.x;
            r[1] += wA * p0.y; r[2] += wA * p0.z; r[3] += wA * p0.w;
            r[4] += wS * p1.x; r[5] += wS * p1.y; r[6] += wS * p1.z;
            r[7] += wS * p1.w; r[8] += wS * v8;
        }

        float Ip = r[0], a01 = r[1], a02 = r[2], a12 = r[3];
        float s00 = r[4], s01 = r[5], s02 = r[6], s11 = r[7], s12 = r[8];
        float s22 = -(s00 + s11);

        const float* ap = g_acc + (size_t)n * 96 + lane * 3;
        float sI = ap[0], sA = ap[1], sS = ap[2];

        float Y[9], G[9];
        Y[0] = Ip + s00;  Y[1] = a01 + s01;  Y[2] = a02 + s02;
        Y[3] = s01 - a01; Y[4] = Ip + s11;   Y[5] = a12 + s12;
        Y[6] = s02 - a02; Y[7] = s12 - a12;  Y[8] = Ip + s22;
        G[0] = Ip*sI + s00*sS;  G[1] = a01*sA + s01*sS;  G[2] = a02*sA + s02*sS;
        G[3] = s01*sS - a01*sA; G[4] = Ip*sI + s11*sS;   G[5] = a12*sA + s12*sS;
        G[6] = s02*sS - a02*sA; G[7] = s12*sS - a12*sA;  G[8] = Ip*sI + s22*sS;

        float M[9];
        #pragma unroll
        for (int i = 0; i < 3; i++)
            #pragma unroll
            for (int l = 0; l < 3; l++) {
                float a2 = 0.0f;
                #pragma unroll
                for (int j = 0; j < 3; j++)
                    a2 += Y[i*3+j] * G[j*3+l] + G[i*3+j] * Y[j*3+l];
                M[i*3+l] = a2;
            }

        float np = 1.0f;
        #pragma unroll
        for (int t = 0; t < 9; t++) np += M[t] * M[t];
        float inv2 = __fdividef(1.0f, np);
        float trm = (M[0] + M[4] + M[8]) * (1.0f / 3.0f);
        c[0] = trm * inv2;
        c[1] = 0.5f * (M[1] - M[3]) * inv2;
        c[2] = 0.5f * (M[2] - M[6]) * inv2;
        c[3] = 0.5f * (M[5] - M[7]) * inv2;
        c[4] = (M[0] - trm) * inv2;
        c[5] = 0.5f * (M[1] + M[3]) * inv2;
        c[6] = 0.5f * (M[2] + M[6]) * inv2;
        c[7] = (M[4] - trm) * inv2;
        c[8] = 0.5f * (M[5] + M[7]) * inv2;

        __syncwarp();
        #pragma unroll
        for (int t = 0; t < 9; t++) vp[lane][t] = c[t];
        __syncwarp();

        float r2[9] = {0,0,0,0,0,0,0,0,0};
        #pragma unroll 8
        for (int k = 0; k < 32; k++) {
            const float4* q4 = reinterpret_cast<const float4*>(&vp[k][0]);
            float4 p0 = q4[0], p1 = q4[1];
            float v8 = vp[k][8];
            float wI = sWt[3][k][lane];
            float wA = sWt[4][k][lane];
            float wS = sWt[5][k][lane];
            r2[0] += wI * p0.x;
            r2[1] += wA * p0.y; r2[2] += wA * p0.z; r2[3] += wA * p0.w;
            r2[4] += wS * p1.x; r2[5] += wS * p1.y; r2[6] += wS * p1.z;
            r2[7] += wS * p1.w; r2[8] += wS * v8;
        }
        __syncwarp();

        float Ip2 = r2[0], b01 = r2[1], b02 = r2[2], b12 = r2[3];
        float t00 = r2[4], t01 = r2[5], t02 = r2[6], t11 = r2[7], t12 = r2[8];
        float t22 = -(t00 + t11);

        float D[9];
        D[0] = Ip2 + t00;  D[1] = b01 + t01;  D[2] = b02 + t02;
        D[3] = t01 - b01;  D[4] = Ip2 + t11;  D[5] = b12 + t12;
        D[6] = t02 - b02;  D[7] = t12 - b12;  D[8] = Ip2 + t22;

        #pragma unroll
        for (int i = 0; i < 3; i++)
            #pragma unroll
            for (int l = 0; l < 3; l++) {
                float o = Xn[i*3+l] + D[i*3+l];
                #pragma unroll
                for (int j = 0; j < 3; j++)
                    o += D[i*3+j] * D[j*3+l];
                out[((size_t)n * 9 + (i*3+l)) * 32 + lane] = o;
            }
    }
}

// ---------------------------------------------------------------------------
extern "C" void kernel_launch(void* const* d_in, const int* in_sizes, int n_in,
                              void* d_out, int out_size)
{
    const float* X           = (const float*)d_in[0];
    const int*   edge_index  = (const int*)  d_in[1];
    const float* edge_weight = (const float*)d_in[2];
    const float* edge_attr   = (const float*)d_in[3];
    const float* W1 = (const float*)d_in[4];
    const float* b1 = (const float*)d_in[5];
    const float* W2 = (const float*)d_in[6];
    const float* b2 = (const float*)d_in[7];
    const float* W3 = (const float*)d_in[8];
    const float* b3 = (const float*)d_in[9];
    const float* Wt = (const float*)d_in[10];
    float* out = (float*)d_out;

    int N = in_sizes[0] / 288;   // X is (N,3,3,32)
    if (N > MAXN) N = MAXN;
    int E = in_sizes[2];         // edge_weight is (E,)

    int n4 = N * 24;
    zero_acc_kernel<<<(n4 + 255) / 256, 256>>>(n4);

    edge_mlp_kernel<<<(E + TPB - 1) / TPB, TPB>>>(
        edge_attr, edge_index, edge_weight, W1, b1, W2, b2, W3, b3, E);

    node_kernel<<<(N + NODE_WARPS - 1) / NODE_WARPS, 32 * NODE_WARPS>>>(
        X, Wt, out, N);
}

// round 5
// speedup vs baseline: 1.8196x; 1.5806x over previous
#include <cuda_runtime.h>
#include <cuda_bf16.h>
#include <cstdint>

// ---------------------------------------------------------------------------
// TensorNet interaction.
//   msg[n] = (component tensors of n) * (per-node scalar sums of edge MLP),
//   so the graph part is a scatter-add of 96 edge-MLP outputs into acc[n][96].
//
// R5: edge MLP on tensor cores via baseline-PTX mma.sync.m16n8k16 bf16
//     (harness toolchain targets compute_103, so tcgen05 is unavailable).
//     bf16x3 split (xh*wh + xl*wh + xh*wl) gives fp32-grade accuracy.
//     C-fragment of layer i == A-fragment of layer i+1 (paired n-tiles), so
//     h1/h2 stay in registers; weights pre-packed in B-fragment order in
//     SMEM. One warp = 16 edges. Persistent grid.
// ---------------------------------------------------------------------------

#define MAXN 50000
#define PI_F 3.14159265358979323846f
#define CUTOFF_F 5.0f

__device__ float g_acc[(size_t)MAXN * 96];

__device__ __forceinline__ float silu_f(float v) {
    return v * __fdividef(1.0f, 1.0f + __expf(-v));
}
// pack two floats as bf16x2 (lo = first arg)
__device__ __forceinline__ uint32_t packbf(float lo, float hi) {
    uint32_t r;
    asm("cvt.rn.bf16x2.f32 %0, %1, %2;" : "=r"(r) : "f"(hi), "f"(lo));
    return r;
}
__device__ __forceinline__ float bf16val(float v) {
    return __bfloat162float(__float2bfloat16(v));
}
// hi pack + residual(lo) pack
__device__ __forceinline__ void pack_hl(float x, float y, uint32_t& h, uint32_t& l) {
    h = packbf(x, y);
    l = packbf(x - bf16val(x), y - bf16val(y));
}

__device__ __forceinline__ void mma_bf16(float c[4], const uint32_t a[4], uint2 b) {
    asm volatile(
        "mma.sync.aligned.m16n8k16.row.col.f32.bf16.bf16.f32 "
        "{%0,%1,%2,%3}, {%4,%5,%6,%7}, {%8,%9}, {%0,%1,%2,%3};"
        : "+f"(c[0]), "+f"(c[1]), "+f"(c[2]), "+f"(c[3])
        : "r"(a[0]), "r"(a[1]), "r"(a[2]), "r"(a[3]), "r"(b.x), "r"(b.y));
}

// ---------------------------------------------------------------------------
// Edge MLP kernel. Warp = 16-edge strip.
// B-fragment packing (m16n8k16, row.col): thread l of a frag (kf, nt) holds
//   b0 = {W[n][k0], W[n][k0+1]}, b1 = {W[n][k0+8], W[n][k0+9]}
//   with n = nt*8 + l/4, k0 = kf*16 + 2*(l%4).
__global__ void __launch_bounds__(256)
edge_mma_kernel(const float* __restrict__ edge_attr,
                const int*   __restrict__ edge_index,
                const float* __restrict__ edge_weight,
                const float* __restrict__ W1, const float* __restrict__ b1,
                const float* __restrict__ W2, const float* __restrict__ b2,
                const float* __restrict__ W3, const float* __restrict__ b3,
                int E)
{
    __shared__ uint2 sB1h[8][32],  sB1l[8][32];    // L1: f = nt*2+kf (nt 0..3)
    __shared__ uint2 sB2h[16][32], sB2l[16][32];   // L2: f = nt*2+kf (nt 0..7)
    __shared__ uint2 sB3h[48][32], sB3l[48][32];   // L3: f = nt*4+kf (nt 0..11)
    __shared__ float sb1[32], sb2[64], sb3[96];

    const int tid = threadIdx.x;

    // ---- pack weights into B-fragment layout ----
    {
        int i = tid;                       // exactly 256 items for L1
        int f = i >> 5, l = i & 31;
        int nt = f >> 1, kf = f & 1;
        int n = nt * 8 + (l >> 2), k0 = kf * 16 + ((l & 3) << 1);
        const float* Wr = W1 + n * 32 + k0;
        float w00 = Wr[0], w01 = Wr[1], w80 = Wr[8], w81 = Wr[9];
        uint32_t h0, l0, h1, l1;
        pack_hl(w00, w01, h0, l0);
        pack_hl(w80, w81, h1, l1);
        sB1h[f][l] = make_uint2(h0, h1);
        sB1l[f][l] = make_uint2(l0, l1);
    }
    for (int i = tid; i < 512; i += 256) {  // L2
        int f = i >> 5, l = i & 31;
        int nt = f >> 1, kf = f & 1;
        int n = nt * 8 + (l >> 2), k0 = kf * 16 + ((l & 3) << 1);
        const float* Wr = W2 + n * 32 + k0;
        float w00 = Wr[0], w01 = Wr[1], w80 = Wr[8], w81 = Wr[9];
        uint32_t h0, l0, h1, l1;
        pack_hl(w00, w01, h0, l0);
        pack_hl(w80, w81, h1, l1);
        sB2h[f][l] = make_uint2(h0, h1);
        sB2l[f][l] = make_uint2(l0, l1);
    }
    for (int i = tid; i < 1536; i += 256) { // L3
        int f = i >> 5, l = i & 31;
        int nt = f >> 2, kf = f & 3;
        int n = nt * 8 + (l >> 2), k0 = kf * 16 + ((l & 3) << 1);
        const float* Wr = W3 + n * 64 + k0;
        float w00 = Wr[0], w01 = Wr[1], w80 = Wr[8], w81 = Wr[9];
        uint32_t h0, l0, h1, l1;
        pack_hl(w00, w01, h0, l0);
        pack_hl(w80, w81, h1, l1);
        sB3h[f][l] = make_uint2(h0, h1);
        sB3l[f][l] = make_uint2(l0, l1);
    }
    if (tid < 32) sb1[tid] = b1[tid];
    if (tid < 64) sb2[tid] = b2[tid];
    if (tid < 96) sb3[tid] = b3[tid];
    __syncthreads();

    const int wid = tid >> 5, lane = tid & 31;
    const int r1 = lane >> 2;          // row within strip (and +8)
    const int q  = (lane & 3) << 1;    // column pair base
    const int nStrips = (E + 15) >> 4;

    for (int strip = blockIdx.x * 8 + wid; strip < nStrips;
         strip += gridDim.x * 8) {
        int e0 = strip << 4;
        int eA = e0 + r1, eB = eA + 8;
        int eAc = min(eA, E - 1), eBc = min(eB, E - 1);

        // ---- load x A-fragments (hi/lo) ----
        uint32_t A1h[2][4], A1l[2][4];
        #pragma unroll
        for (int kf = 0; kf < 2; kf++) {
            const float* pa = edge_attr + (size_t)eAc * 32 + kf * 16 + q;
            const float* pb = edge_attr + (size_t)eBc * 32 + kf * 16 + q;
            float2 v0 = *(const float2*)pa;        // row r1, k-half 0
            float2 v1 = *(const float2*)pb;        // row r2, k-half 0
            float2 v2 = *(const float2*)(pa + 8);  // row r1, k-half 1
            float2 v3 = *(const float2*)(pb + 8);  // row r2, k-half 1
            pack_hl(v0.x, v0.y, A1h[kf][0], A1l[kf][0]);
            pack_hl(v1.x, v1.y, A1h[kf][1], A1l[kf][1]);
            pack_hl(v2.x, v2.y, A1h[kf][2], A1l[kf][2]);
            pack_hl(v3.x, v3.y, A1h[kf][3], A1l[kf][3]);
        }

        // ---- Layer 1: D1[16x32] = X @ W1^T + b1 ----
        float D1[4][4];
        #pragma unroll
        for (int nt = 0; nt < 4; nt++) {
            float bb0 = sb1[nt * 8 + q], bb1 = sb1[nt * 8 + q + 1];
            D1[nt][0] = bb0; D1[nt][1] = bb1; D1[nt][2] = bb0; D1[nt][3] = bb1;
            #pragma unroll
            for (int kf = 0; kf < 2; kf++) {
                uint2 Bh = sB1h[nt * 2 + kf][lane];
                uint2 Bl = sB1l[nt * 2 + kf][lane];
                mma_bf16(D1[nt], A1h[kf], Bh);
                mma_bf16(D1[nt], A1l[kf], Bh);
                mma_bf16(D1[nt], A1h[kf], Bl);
            }
        }

        // ---- silu -> A2 fragments (in-register C->A identity) ----
        uint32_t A2h[2][4], A2l[2][4];
        #pragma unroll
        for (int kf = 0; kf < 2; kf++) {
            int na = 2 * kf, nb = 2 * kf + 1;
            float sa0 = silu_f(D1[na][0]), sa1 = silu_f(D1[na][1]);
            float sa2 = silu_f(D1[na][2]), sa3 = silu_f(D1[na][3]);
            float sb0 = silu_f(D1[nb][0]), sb1v = silu_f(D1[nb][1]);
            float sb2v = silu_f(D1[nb][2]), sb3v = silu_f(D1[nb][3]);
            pack_hl(sa0, sa1, A2h[kf][0], A2l[kf][0]);
            pack_hl(sa2, sa3, A2h[kf][1], A2l[kf][1]);
            pack_hl(sb0, sb1v, A2h[kf][2], A2l[kf][2]);
            pack_hl(sb2v, sb3v, A2h[kf][3], A2l[kf][3]);
        }

        // ---- Layer 2: D2[16x64] = H1 @ W2^T + b2 ----
        float D2[8][4];
        #pragma unroll
        for (int nt = 0; nt < 8; nt++) {
            float bb0 = sb2[nt * 8 + q], bb1 = sb2[nt * 8 + q + 1];
            D2[nt][0] = bb0; D2[nt][1] = bb1; D2[nt][2] = bb0; D2[nt][3] = bb1;
            #pragma unroll
            for (int kf = 0; kf < 2; kf++) {
                uint2 Bh = sB2h[nt * 2 + kf][lane];
                uint2 Bl = sB2l[nt * 2 + kf][lane];
                mma_bf16(D2[nt], A2h[kf], Bh);
                mma_bf16(D2[nt], A2l[kf], Bh);
                mma_bf16(D2[nt], A2h[kf], Bl);
            }
        }

        // ---- silu -> A3 fragments ----
        uint32_t A3h[4][4], A3l[4][4];
        #pragma unroll
        for (int kf = 0; kf < 4; kf++) {
            int na = 2 * kf, nb = 2 * kf + 1;
            float sa0 = silu_f(D2[na][0]), sa1 = silu_f(D2[na][1]);
            float sa2 = silu_f(D2[na][2]), sa3 = silu_f(D2[na][3]);
            float sb0 = silu_f(D2[nb][0]), sb1v = silu_f(D2[nb][1]);
            float sb2v = silu_f(D2[nb][2]), sb3v = silu_f(D2[nb][3]);
            pack_hl(sa0, sa1, A3h[kf][0], A3l[kf][0]);
            pack_hl(sa2, sa3, A3h[kf][1], A3l[kf][1]);
            pack_hl(sb0, sb1v, A3h[kf][2], A3l[kf][2]);
            pack_hl(sb2v, sb3v, A3h[kf][3], A3l[kf][3]);
        }

        // ---- Layer 3: D3[16x96] = H2 @ W3^T + b3 ----
        float D3[12][4];
        #pragma unroll
        for (int nt = 0; nt < 12; nt++) {
            float bb0 = sb3[nt * 8 + q], bb1 = sb3[nt * 8 + q + 1];
            D3[nt][0] = bb0; D3[nt][1] = bb1; D3[nt][2] = bb0; D3[nt][3] = bb1;
            #pragma unroll
            for (int kf = 0; kf < 4; kf++) {
                uint2 Bh = sB3h[nt * 4 + kf][lane];
                uint2 Bl = sB3l[nt * 4 + kf][lane];
                mma_bf16(D3[nt], A3h[kf], Bh);
                mma_bf16(D3[nt], A3l[kf], Bh);
                mma_bf16(D3[nt], A3h[kf], Bl);
            }
        }

        // ---- epilogue: silu * cutoff, scatter-add ----
        float wA = edge_weight[eAc], wB = edge_weight[eBc];
        float CcA = (wA < CUTOFF_F)
                  ? 0.5f * (__cosf(wA * (PI_F / CUTOFF_F)) + 1.0f) : 0.0f;
        float CcB = (wB < CUTOFF_F)
                  ? 0.5f * (__cosf(wB * (PI_F / CUTOFF_F)) + 1.0f) : 0.0f;
        int dA = edge_index[E + eAc], dB = edge_index[E + eBc];
        bool okA = eA < E, okB = eB < E;
        float* gA = g_acc + (size_t)dA * 96 + q;
        float* gB = g_acc + (size_t)dB * 96 + q;

        #pragma unroll
        for (int nt = 0; nt < 12; nt++) {
            if (okA) {
                float t0 = silu_f(D3[nt][0]) * CcA;
                float t1 = silu_f(D3[nt][1]) * CcA;
                asm volatile("red.global.add.v2.f32 [%0], {%1, %2};"
                             :: "l"(gA + nt * 8), "f"(t0), "f"(t1) : "memory");
            }
            if (okB) {
                float t2 = silu_f(D3[nt][2]) * CcB;
                float t3 = silu_f(D3[nt][3]) * CcB;
                asm volatile("red.global.add.v2.f32 [%0], {%1, %2};"
                             :: "l"(gB + nt * 8), "f"(t2), "f"(t3) : "memory");
            }
        }
    }
}

// ---------------------------------------------------------------------------
// Node kernel: one warp per node, lane = unit (U=32). Re-zeros g_acc.
#define NODE_WARPS 8
__global__ void __launch_bounds__(32 * NODE_WARPS)
node_kernel(const float* __restrict__ X,
            const float* __restrict__ Wt,
            float* __restrict__ out,
            int nNodes)
{
    __shared__ float sWt[6][32][32];            // sWt[c][k][m] = Wt[c][m][k]
    __shared__ float vst[NODE_WARPS][32][12];

    for (int i = threadIdx.x; i < 6144; i += 32 * NODE_WARPS) {
        int c = i >> 10, r = i & 1023;
        int mm = r >> 5, k = r & 31;
        sWt[c][k][mm] = Wt[i];
    }
    __syncthreads();

    int warpId = threadIdx.x >> 5;
    int lane   = threadIdx.x & 31;
    float (*vp)[12] = vst[warpId];

    for (int n = blockIdx.x * NODE_WARPS + warpId; n < nNodes;
         n += gridDim.x * NODE_WARPS) {

        float Xn[9];
        float nrm = 1.0f;
        #pragma unroll
        for (int t = 0; t < 9; t++) {
            float v = X[((size_t)n * 9 + t) * 32 + lane];
            Xn[t] = v; nrm += v * v;
        }
        float inv = __fdividef(1.0f, nrm);
        #pragma unroll
        for (int t = 0; t < 9; t++) Xn[t] *= inv;

        float tr3 = (Xn[0] + Xn[4] + Xn[8]) * (1.0f / 3.0f);
        float c[9];
        c[0] = tr3;
        c[1] = 0.5f * (Xn[1] - Xn[3]);
        c[2] = 0.5f * (Xn[2] - Xn[6]);
        c[3] = 0.5f * (Xn[5] - Xn[7]);
        c[4] = Xn[0] - tr3;
        c[5] = 0.5f * (Xn[1] + Xn[3]);
        c[6] = 0.5f * (Xn[2] + Xn[6]);
        c[7] = Xn[4] - tr3;
        c[8] = 0.5f * (Xn[5] + Xn[7]);

        __syncwarp();
        #pragma unroll
        for (int t = 0; t < 9; t++) vp[lane][t] = c[t];
        __syncwarp();

        float r[9] = {0,0,0,0,0,0,0,0,0};
        #pragma unroll 8
        for (int k = 0; k < 32; k++) {
            const float4* q4 = reinterpret_cast<const float4*>(&vp[k][0]);
            float4 p0 = q4[0], p1 = q4[1];
            float v8 = vp[k][8];
            float wI = sWt[0][k][lane];
            float wA = sWt[1][k][lane];
            float wS = sWt[2][k][lane];
            r[0] += wI * p0.x;
            r[1] += wA * p0.y; r[2] += wA * p0.z; r[3] += wA * p0.w;
            r[4] += wS * p1.x; r[5] += wS * p1.y; r[6] += wS * p1.z;
            r[7] += wS * p1.w; r[8] += wS * v8;
        }

        float Ip = r[0], a01 = r[1], a02 = r[2], a12 = r[3];
        float s00 = r[4], s01 = r[5], s02 = r[6], s11 = r[7], s12 = r[8];
        float s22 = -(s00 + s11);

        float* ap = g_acc + (size_t)n * 96 + lane * 3;
        float sI = ap[0], sA = ap[1], sS = ap[2];
        ap[0] = 0.0f; ap[1] = 0.0f; ap[2] = 0.0f;   // re-zero for next launch

        float Y[9], G[9];
        Y[0] = Ip + s00;  Y[1] = a01 + s01;  Y[2] = a02 + s02;
        Y[3] = s01 - a01; Y[4] = Ip + s11;   Y[5] = a12 + s12;
        Y[6] = s02 - a02; Y[7] = s12 - a12;  Y[8] = Ip + s22;
        G[0] = Ip*sI + s00*sS;  G[1] = a01*sA + s01*sS;  G[2] = a02*sA + s02*sS;
        G[3] = s01*sS - a01*sA; G[4] = Ip*sI + s11*sS;   G[5] = a12*sA + s12*sS;
        G[6] = s02*sS - a02*sA; G[7] = s12*sS - a12*sA;  G[8] = Ip*sI + s22*sS;

        float M[9];
        #pragma unroll
        for (int i = 0; i < 3; i++)
            #pragma unroll
            for (int l = 0; l < 3; l++) {
                float a2 = 0.0f;
                #pragma unroll
                for (int j = 0; j < 3; j++)
                    a2 += Y[i*3+j] * G[j*3+l] + G[i*3+j] * Y[j*3+l];
                M[i*3+l] = a2;
            }

        float np = 1.0f;
        #pragma unroll
        for (int t = 0; t < 9; t++) np += M[t] * M[t];
        float inv2 = __fdividef(1.0f, np);
        float trm = (M[0] + M[4] + M[8]) * (1.0f / 3.0f);
        c[0] = trm * inv2;
        c[1] = 0.5f * (M[1] - M[3]) * inv2;
        c[2] = 0.5f * (M[2] - M[6]) * inv2;
        c[3] = 0.5f * (M[5] - M[7]) * inv2;
        c[4] = (M[0] - trm) * inv2;
        c[5] = 0.5f * (M[1] + M[3]) * inv2;
        c[6] = 0.5f * (M[2] + M[6]) * inv2;
        c[7] = (M[4] - trm) * inv2;
        c[8] = 0.5f * (M[5] + M[7]) * inv2;

        __syncwarp();
        #pragma unroll
        for (int t = 0; t < 9; t++) vp[lane][t] = c[t];
        __syncwarp();

        float r2[9] = {0,0,0,0,0,0,0,0,0};
        #pragma unroll 8
        for (int k = 0; k < 32; k++) {
            const float4* q4 = reinterpret_cast<const float4*>(&vp[k][0]);
            float4 p0 = q4[0], p1 = q4[1];
            float v8 = vp[k][8];
            float wI = sWt[3][k][lane];
            float wA = sWt[4][k][lane];
            float wS = sWt[5][k][lane];
            r2[0] += wI * p0.x;
            r2[1] += wA * p0.y; r2[2] += wA * p0.z; r2[3] += wA * p0.w;
            r2[4] += wS * p1.x; r2[5] += wS * p1.y; r2[6] += wS * p1.z;
            r2[7] += wS * p1.w; r2[8] += wS * v8;
        }
        __syncwarp();

        float Ip2 = r2[0], b01 = r2[1], b02 = r2[2], b12 = r2[3];
        float t00 = r2[4], t01 = r2[5], t02 = r2[6], t11 = r2[7], t12 = r2[8];
        float t22 = -(t00 + t11);

        float D[9];
        D[0] = Ip2 + t00;  D[1] = b01 + t01;  D[2] = b02 + t02;
        D[3] = t01 - b01;  D[4] = Ip2 + t11;  D[5] = b12 + t12;
        D[6] = t02 - b02;  D[7] = t12 - b12;  D[8] = Ip2 + t22;

        #pragma unroll
        for (int i = 0; i < 3; i++)
            #pragma unroll
            for (int l = 0; l < 3; l++) {
                float o = Xn[i*3+l] + D[i*3+l];
                #pragma unroll
                for (int j = 0; j < 3; j++)
                    o += D[i*3+j] * D[j*3+l];
                out[((size_t)n * 9 + (i*3+l)) * 32 + lane] = o;
            }
    }
}

// ---------------------------------------------------------------------------
extern "C" void kernel_launch(void* const* d_in, const int* in_sizes, int n_in,
                              void* d_out, int out_size)
{
    const float* X           = (const float*)d_in[0];
    const int*   edge_index  = (const int*)  d_in[1];
    const float* edge_weight = (const float*)d_in[2];
    const float* edge_attr   = (const float*)d_in[3];
    const float* W1 = (const float*)d_in[4];
    const float* b1 = (const float*)d_in[5];
    const float* W2 = (const float*)d_in[6];
    const float* b2 = (const float*)d_in[7];
    const float* W3 = (const float*)d_in[8];
    const float* b3 = (const float*)d_in[9];
    const float* Wt = (const float*)d_in[10];
    float* out = (float*)d_out;

    int N = in_sizes[0] / 288;   // X is (N,3,3,32)
    if (N > MAXN) N = MAXN;
    int E = in_sizes[2];         // edge_weight is (E,)

    int nStrips = (E + 15) >> 4;
    int grid = (nStrips + 7) / 8;
    if (grid > 296) grid = 296;

    edge_mma_kernel<<<grid, 256>>>(
        edge_attr, edge_index, edge_weight, W1, b1, W2, b2, W3, b3, E);

    node_kernel<<<(N + NODE_WARPS - 1) / NODE_WARPS, 32 * NODE_WARPS>>>(
        X, Wt, out, N);
}

// round 6
// speedup vs baseline: 2.6249x; 1.4426x over previous
#include <cuda_runtime.h>
#include <cuda_bf16.h>
#include <cstdint>

// ---------------------------------------------------------------------------
// TensorNet interaction.
//   msg[n] = (component tensors of n) * (per-node scalar sums of edge MLP),
//   so the graph part is a scatter-add of 96 edge-MLP outputs into acc[n][96].
//
// R6: node_kernel launched persistent (592 blocks) so the 24KB Wt SMEM
//     staging is amortized over ~84 nodes/block instead of 8 (R5 launched
//     6250 blocks -> 150MB redundant weight traffic + per-block sync wall).
//     Edge MLP unchanged: mma.sync bf16x3 (fp32-grade), register-resident
//     h1/h2 via the C->A fragment identity, REDG v2 scatter.
// ---------------------------------------------------------------------------

#define MAXN 50000
#define PI_F 3.14159265358979323846f
#define CUTOFF_F 5.0f

__device__ float g_acc[(size_t)MAXN * 96];

__device__ __forceinline__ float silu_f(float v) {
    return v * __fdividef(1.0f, 1.0f + __expf(-v));
}
// pack two floats as bf16x2 (lo = first arg)
__device__ __forceinline__ uint32_t packbf(float lo, float hi) {
    uint32_t r;
    asm("cvt.rn.bf16x2.f32 %0, %1, %2;" : "=r"(r) : "f"(hi), "f"(lo));
    return r;
}
__device__ __forceinline__ float bf16val(float v) {
    return __bfloat162float(__float2bfloat16(v));
}
// hi pack + residual(lo) pack
__device__ __forceinline__ void pack_hl(float x, float y, uint32_t& h, uint32_t& l) {
    h = packbf(x, y);
    l = packbf(x - bf16val(x), y - bf16val(y));
}

__device__ __forceinline__ void mma_bf16(float c[4], const uint32_t a[4], uint2 b) {
    asm volatile(
        "mma.sync.aligned.m16n8k16.row.col.f32.bf16.bf16.f32 "
        "{%0,%1,%2,%3}, {%4,%5,%6,%7}, {%8,%9}, {%0,%1,%2,%3};"
        : "+f"(c[0]), "+f"(c[1]), "+f"(c[2]), "+f"(c[3])
        : "r"(a[0]), "r"(a[1]), "r"(a[2]), "r"(a[3]), "r"(b.x), "r"(b.y));
}

// ---------------------------------------------------------------------------
// Edge MLP kernel. Warp = 16-edge strip.
__global__ void __launch_bounds__(256)
edge_mma_kernel(const float* __restrict__ edge_attr,
                const int*   __restrict__ edge_index,
                const float* __restrict__ edge_weight,
                const float* __restrict__ W1, const float* __restrict__ b1,
                const float* __restrict__ W2, const float* __restrict__ b2,
                const float* __restrict__ W3, const float* __restrict__ b3,
                int E)
{
    __shared__ uint2 sB1h[8][32],  sB1l[8][32];    // L1: f = nt*2+kf (nt 0..3)
    __shared__ uint2 sB2h[16][32], sB2l[16][32];   // L2: f = nt*2+kf (nt 0..7)
    __shared__ uint2 sB3h[48][32], sB3l[48][32];   // L3: f = nt*4+kf (nt 0..11)
    __shared__ float sb1[32], sb2[64], sb3[96];

    const int tid = threadIdx.x;

    // ---- pack weights into B-fragment layout ----
    {
        int i = tid;                       // exactly 256 items for L1
        int f = i >> 5, l = i & 31;
        int nt = f >> 1, kf = f & 1;
        int n = nt * 8 + (l >> 2), k0 = kf * 16 + ((l & 3) << 1);
        const float* Wr = W1 + n * 32 + k0;
        float w00 = Wr[0], w01 = Wr[1], w80 = Wr[8], w81 = Wr[9];
        uint32_t h0, l0, h1, l1;
        pack_hl(w00, w01, h0, l0);
        pack_hl(w80, w81, h1, l1);
        sB1h[f][l] = make_uint2(h0, h1);
        sB1l[f][l] = make_uint2(l0, l1);
    }
    for (int i = tid; i < 512; i += 256) {  // L2
        int f = i >> 5, l = i & 31;
        int nt = f >> 1, kf = f & 1;
        int n = nt * 8 + (l >> 2), k0 = kf * 16 + ((l & 3) << 1);
        const float* Wr = W2 + n * 32 + k0;
        float w00 = Wr[0], w01 = Wr[1], w80 = Wr[8], w81 = Wr[9];
        uint32_t h0, l0, h1, l1;
        pack_hl(w00, w01, h0, l0);
        pack_hl(w80, w81, h1, l1);
        sB2h[f][l] = make_uint2(h0, h1);
        sB2l[f][l] = make_uint2(l0, l1);
    }
    for (int i = tid; i < 1536; i += 256) { // L3
        int f = i >> 5, l = i & 31;
        int nt = f >> 2, kf = f & 3;
        int n = nt * 8 + (l >> 2), k0 = kf * 16 + ((l & 3) << 1);
        const float* Wr = W3 + n * 64 + k0;
        float w00 = Wr[0], w01 = Wr[1], w80 = Wr[8], w81 = Wr[9];
        uint32_t h0, l0, h1, l1;
        pack_hl(w00, w01, h0, l0);
        pack_hl(w80, w81, h1, l1);
        sB3h[f][l] = make_uint2(h0, h1);
        sB3l[f][l] = make_uint2(l0, l1);
    }
    if (tid < 32) sb1[tid] = b1[tid];
    if (tid < 64) sb2[tid] = b2[tid];
    if (tid < 96) sb3[tid] = b3[tid];
    __syncthreads();

    const int wid = tid >> 5, lane = tid & 31;
    const int r1 = lane >> 2;          // row within strip (and +8)
    const int q  = (lane & 3) << 1;    // column pair base
    const int nStrips = (E + 15) >> 4;

    for (int strip = blockIdx.x * 8 + wid; strip < nStrips;
         strip += gridDim.x * 8) {
        int e0 = strip << 4;
        int eA = e0 + r1, eB = eA + 8;
        int eAc = min(eA, E - 1), eBc = min(eB, E - 1);

        // ---- load x A-fragments (hi/lo) ----
        uint32_t A1h[2][4], A1l[2][4];
        #pragma unroll
        for (int kf = 0; kf < 2; kf++) {
            const float* pa = edge_attr + (size_t)eAc * 32 + kf * 16 + q;
            const float* pb = edge_attr + (size_t)eBc * 32 + kf * 16 + q;
            float2 v0 = *(const float2*)pa;
            float2 v1 = *(const float2*)pb;
            float2 v2 = *(const float2*)(pa + 8);
            float2 v3 = *(const float2*)(pb + 8);
            pack_hl(v0.x, v0.y, A1h[kf][0], A1l[kf][0]);
            pack_hl(v1.x, v1.y, A1h[kf][1], A1l[kf][1]);
            pack_hl(v2.x, v2.y, A1h[kf][2], A1l[kf][2]);
            pack_hl(v3.x, v3.y, A1h[kf][3], A1l[kf][3]);
        }

        // ---- Layer 1: D1[16x32] = X @ W1^T + b1 ----
        float D1[4][4];
        #pragma unroll
        for (int nt = 0; nt < 4; nt++) {
            float bb0 = sb1[nt * 8 + q], bb1 = sb1[nt * 8 + q + 1];
            D1[nt][0] = bb0; D1[nt][1] = bb1; D1[nt][2] = bb0; D1[nt][3] = bb1;
            #pragma unroll
            for (int kf = 0; kf < 2; kf++) {
                uint2 Bh = sB1h[nt * 2 + kf][lane];
                uint2 Bl = sB1l[nt * 2 + kf][lane];
                mma_bf16(D1[nt], A1h[kf], Bh);
                mma_bf16(D1[nt], A1l[kf], Bh);
                mma_bf16(D1[nt], A1h[kf], Bl);
            }
        }

        // ---- silu -> A2 fragments (in-register C->A identity) ----
        uint32_t A2h[2][4], A2l[2][4];
        #pragma unroll
        for (int kf = 0; kf < 2; kf++) {
            int na = 2 * kf, nb = 2 * kf + 1;
            float sa0 = silu_f(D1[na][0]), sa1 = silu_f(D1[na][1]);
            float sa2 = silu_f(D1[na][2]), sa3 = silu_f(D1[na][3]);
            float sb0 = silu_f(D1[nb][0]), sb1v = silu_f(D1[nb][1]);
            float sb2v = silu_f(D1[nb][2]), sb3v = silu_f(D1[nb][3]);
            pack_hl(sa0, sa1, A2h[kf][0], A2l[kf][0]);
            pack_hl(sa2, sa3, A2h[kf][1], A2l[kf][1]);
            pack_hl(sb0, sb1v, A2h[kf][2], A2l[kf][2]);
            pack_hl(sb2v, sb3v, A2h[kf][3], A2l[kf][3]);
        }

        // ---- Layer 2: D2[16x64] = H1 @ W2^T + b2 ----
        float D2[8][4];
        #pragma unroll
        for (int nt = 0; nt < 8; nt++) {
            float bb0 = sb2[nt * 8 + q], bb1 = sb2[nt * 8 + q + 1];
            D2[nt][0] = bb0; D2[nt][1] = bb1; D2[nt][2] = bb0; D2[nt][3] = bb1;
            #pragma unroll
            for (int kf = 0; kf < 2; kf++) {
                uint2 Bh = sB2h[nt * 2 + kf][lane];
                uint2 Bl = sB2l[nt * 2 + kf][lane];
                mma_bf16(D2[nt], A2h[kf], Bh);
                mma_bf16(D2[nt], A2l[kf], Bh);
                mma_bf16(D2[nt], A2h[kf], Bl);
            }
        }

        // ---- silu -> A3 fragments ----
        uint32_t A3h[4][4], A3l[4][4];
        #pragma unroll
        for (int kf = 0; kf < 4; kf++) {
            int na = 2 * kf, nb = 2 * kf + 1;
            float sa0 = silu_f(D2[na][0]), sa1 = silu_f(D2[na][1]);
            float sa2 = silu_f(D2[na][2]), sa3 = silu_f(D2[na][3]);
            float sb0 = silu_f(D2[nb][0]), sb1v = silu_f(D2[nb][1]);
            float sb2v = silu_f(D2[nb][2]), sb3v = silu_f(D2[nb][3]);
            pack_hl(sa0, sa1, A3h[kf][0], A3l[kf][0]);
            pack_hl(sa2, sa3, A3h[kf][1], A3l[kf][1]);
            pack_hl(sb0, sb1v, A3h[kf][2], A3l[kf][2]);
            pack_hl(sb2v, sb3v, A3h[kf][3], A3l[kf][3]);
        }

        // ---- Layer 3: D3[16x96] = H2 @ W3^T + b3 ----
        float D3[12][4];
        #pragma unroll
        for (int nt = 0; nt < 12; nt++) {
            float bb0 = sb3[nt * 8 + q], bb1 = sb3[nt * 8 + q + 1];
            D3[nt][0] = bb0; D3[nt][1] = bb1; D3[nt][2] = bb0; D3[nt][3] = bb1;
            #pragma unroll
            for (int kf = 0; kf < 4; kf++) {
                uint2 Bh = sB3h[nt * 4 + kf][lane];
                uint2 Bl = sB3l[nt * 4 + kf][lane];
                mma_bf16(D3[nt], A3h[kf], Bh);
                mma_bf16(D3[nt], A3l[kf], Bh);
                mma_bf16(D3[nt], A3h[kf], Bl);
            }
        }

        // ---- epilogue: silu * cutoff, scatter-add ----
        float wA = edge_weight[eAc], wB = edge_weight[eBc];
        float CcA = (wA < CUTOFF_F)
                  ? 0.5f * (__cosf(wA * (PI_F / CUTOFF_F)) + 1.0f) : 0.0f;
        float CcB = (wB < CUTOFF_F)
                  ? 0.5f * (__cosf(wB * (PI_F / CUTOFF_F)) + 1.0f) : 0.0f;
        int dA = edge_index[E + eAc], dB = edge_index[E + eBc];
        bool okA = eA < E, okB = eB < E;
        float* gA = g_acc + (size_t)dA * 96 + q;
        float* gB = g_acc + (size_t)dB * 96 + q;

        #pragma unroll
        for (int nt = 0; nt < 12; nt++) {
            if (okA) {
                float t0 = silu_f(D3[nt][0]) * CcA;
                float t1 = silu_f(D3[nt][1]) * CcA;
                asm volatile("red.global.add.v2.f32 [%0], {%1, %2};"
                             :: "l"(gA + nt * 8), "f"(t0), "f"(t1) : "memory");
            }
            if (okB) {
                float t2 = silu_f(D3[nt][2]) * CcB;
                float t3 = silu_f(D3[nt][3]) * CcB;
                asm volatile("red.global.add.v2.f32 [%0], {%1, %2};"
                             :: "l"(gB + nt * 8), "f"(t2), "f"(t3) : "memory");
            }
        }
    }
}

// ---------------------------------------------------------------------------
// Node kernel: one warp per node iteration, lane = unit. Persistent grid:
// weights staged once per block, grid-stride over nodes. Re-zeros g_acc.
#define NODE_WARPS 8
__global__ void __launch_bounds__(32 * NODE_WARPS)
node_kernel(const float* __restrict__ X,
            const float* __restrict__ Wt,
            float* __restrict__ out,
            int nNodes)
{
    __shared__ float sWt[6][32][32];            // sWt[c][k][m] = Wt[c][m][k]
    __shared__ float vst[NODE_WARPS][32][12];

    for (int i = threadIdx.x; i < 6144; i += 32 * NODE_WARPS) {
        int c = i >> 10, r = i & 1023;
        int mm = r >> 5, k = r & 31;
        sWt[c][k][mm] = Wt[i];
    }
    __syncthreads();

    int warpId = threadIdx.x >> 5;
    int lane   = threadIdx.x & 31;
    float (*vp)[12] = vst[warpId];

    for (int n = blockIdx.x * NODE_WARPS + warpId; n < nNodes;
         n += gridDim.x * NODE_WARPS) {

        float Xn[9];
        float nrm = 1.0f;
        #pragma unroll
        for (int t = 0; t < 9; t++) {
            float v = X[((size_t)n * 9 + t) * 32 + lane];
            Xn[t] = v; nrm += v * v;
        }
        float inv = __fdividef(1.0f, nrm);
        #pragma unroll
        for (int t = 0; t < 9; t++) Xn[t] *= inv;

        float tr3 = (Xn[0] + Xn[4] + Xn[8]) * (1.0f / 3.0f);
        float c[9];
        c[0] = tr3;
        c[1] = 0.5f * (Xn[1] - Xn[3]);
        c[2] = 0.5f * (Xn[2] - Xn[6]);
        c[3] = 0.5f * (Xn[5] - Xn[7]);
        c[4] = Xn[0] - tr3;
        c[5] = 0.5f * (Xn[1] + Xn[3]);
        c[6] = 0.5f * (Xn[2] + Xn[6]);
        c[7] = Xn[4] - tr3;
        c[8] = 0.5f * (Xn[5] + Xn[7]);

        __syncwarp();
        #pragma unroll
        for (int t = 0; t < 9; t++) vp[lane][t] = c[t];
        __syncwarp();

        float r[9] = {0,0,0,0,0,0,0,0,0};
        #pragma unroll 8
        for (int k = 0; k < 32; k++) {
            const float4* q4 = reinterpret_cast<const float4*>(&vp[k][0]);
            float4 p0 = q4[0], p1 = q4[1];
            float v8 = vp[k][8];
            float wI = sWt[0][k][lane];
            float wA = sWt[1][k][lane];
            float wS = sWt[2][k][lane];
            r[0] += wI * p0.x;
            r[1] += wA * p0.y; r[2] += wA * p0.z; r[3] += wA * p0.w;
            r[4] += wS * p1.x; r[5] += wS * p1.y; r[6] += wS * p1.z;
            r[7] += wS * p1.w; r[8] += wS * v8;
        }

        float Ip = r[0], a01 = r[1], a02 = r[2], a12 = r[3];
        float s00 = r[4], s01 = r[5], s02 = r[6], s11 = r[7], s12 = r[8];
        float s22 = -(s00 + s11);

        float* ap = g_acc + (size_t)n * 96 + lane * 3;
        float sI = ap[0], sA = ap[1], sS = ap[2];
        ap[0] = 0.0f; ap[1] = 0.0f; ap[2] = 0.0f;   // re-zero for next launch

        float Y[9], G[9];
        Y[0] = Ip + s00;  Y[1] = a01 + s01;  Y[2] = a02 + s02;
        Y[3] = s01 - a01; Y[4] = Ip + s11;   Y[5] = a12 + s12;
        Y[6] = s02 - a02; Y[7] = s12 - a12;  Y[8] = Ip + s22;
        G[0] = Ip*sI + s00*sS;  G[1] = a01*sA + s01*sS;  G[2] = a02*sA + s02*sS;
        G[3] = s01*sS - a01*sA; G[4] = Ip*sI + s11*sS;   G[5] = a12*sA + s12*sS;
        G[6] = s02*sS - a02*sA; G[7] = s12*sS - a12*sA;  G[8] = Ip*sI + s22*sS;

        float M[9];
        #pragma unroll
        for (int i = 0; i < 3; i++)
            #pragma unroll
            for (int l = 0; l < 3; l++) {
                float a2 = 0.0f;
                #pragma unroll
                for (int j = 0; j < 3; j++)
                    a2 += Y[i*3+j] * G[j*3+l] + G[i*3+j] * Y[j*3+l];
                M[i*3+l] = a2;
            }

        float np = 1.0f;
        #pragma unroll
        for (int t = 0; t < 9; t++) np += M[t] * M[t];
        float inv2 = __fdividef(1.0f, np);
        float trm = (M[0] + M[4] + M[8]) * (1.0f / 3.0f);
        c[0] = trm * inv2;
        c[1] = 0.5f * (M[1] - M[3]) * inv2;
        c[2] = 0.5f * (M[2] - M[6]) * inv2;
        c[3] = 0.5f * (M[5] - M[7]) * inv2;
        c[4] = (M[0] - trm) * inv2;
        c[5] = 0.5f * (M[1] + M[3]) * inv2;
        c[6] = 0.5f * (M[2] + M[6]) * inv2;
        c[7] = (M[4] - trm) * inv2;
        c[8] = 0.5f * (M[5] + M[7]) * inv2;

        __syncwarp();
        #pragma unroll
        for (int t = 0; t < 9; t++) vp[lane][t] = c[t];
        __syncwarp();

        float r2[9] = {0,0,0,0,0,0,0,0,0};
        #pragma unroll 8
        for (int k = 0; k < 32; k++) {
            const float4* q4 = reinterpret_cast<const float4*>(&vp[k][0]);
            float4 p0 = q4[0], p1 = q4[1];
            float v8 = vp[k][8];
            float wI = sWt[3][k][lane];
            float wA = sWt[4][k][lane];
            float wS = sWt[5][k][lane];
            r2[0] += wI * p0.x;
            r2[1] += wA * p0.y; r2[2] += wA * p0.z; r2[3] += wA * p0.w;
            r2[4] += wS * p1.x; r2[5] += wS * p1.y; r2[6] += wS * p1.z;
            r2[7] += wS * p1.w; r2[8] += wS * v8;
        }
        __syncwarp();

        float Ip2 = r2[0], b01 = r2[1], b02 = r2[2], b12 = r2[3];
        float t00 = r2[4], t01 = r2[5], t02 = r2[6], t11 = r2[7], t12 = r2[8];
        float t22 = -(t00 + t11);

        float D[9];
        D[0] = Ip2 + t00;  D[1] = b01 + t01;  D[2] = b02 + t02;
        D[3] = t01 - b01;  D[4] = Ip2 + t11;  D[5] = b12 + t12;
        D[6] = t02 - b02;  D[7] = t12 - b12;  D[8] = Ip2 + t22;

        #pragma unroll
        for (int i = 0; i < 3; i++)
            #pragma unroll
            for (int l = 0; l < 3; l++) {
                float o = Xn[i*3+l] + D[i*3+l];
                #pragma unroll
                for (int j = 0; j < 3; j++)
                    o += D[i*3+j] * D[j*3+l];
                out[((size_t)n * 9 + (i*3+l)) * 32 + lane] = o;
            }
    }
}

// ---------------------------------------------------------------------------
extern "C" void kernel_launch(void* const* d_in, const int* in_sizes, int n_in,
                              void* d_out, int out_size)
{
    const float* X           = (const float*)d_in[0];
    const int*   edge_index  = (const int*)  d_in[1];
    const float* edge_weight = (const float*)d_in[2];
    const float* edge_attr   = (const float*)d_in[3];
    const float* W1 = (const float*)d_in[4];
    const float* b1 = (const float*)d_in[5];
    const float* W2 = (const float*)d_in[6];
    const float* b2 = (const float*)d_in[7];
    const float* W3 = (const float*)d_in[8];
    const float* b3 = (const float*)d_in[9];
    const float* Wt = (const float*)d_in[10];
    float* out = (float*)d_out;

    int N = in_sizes[0] / 288;   // X is (N,3,3,32)
    if (N > MAXN) N = MAXN;
    int E = in_sizes[2];         // edge_weight is (E,)

    int nStrips = (E + 15) >> 4;
    int grid = (nStrips + 7) / 8;
    if (grid > 296) grid = 296;

    edge_mma_kernel<<<grid, 256>>>(
        edge_attr, edge_index, edge_weight, W1, b1, W2, b2, W3, b3, E);

    // Persistent node grid: stage weights once per block, grid-stride nodes.
    int nodeBlocks = (N + NODE_WARPS - 1) / NODE_WARPS;
    if (nodeBlocks > 592) nodeBlocks = 592;
    node_kernel<<<nodeBlocks, 32 * NODE_WARPS>>>(X, Wt, out, N);
}

// round 7
// speedup vs baseline: 3.6224x; 1.3800x over previous
#include <cuda_runtime.h>
#include <cuda_bf16.h>
#include <cstdint>

// ---------------------------------------------------------------------------
// TensorNet interaction.
//   msg[n] = (component tensors of n) * (per-node scalar sums of edge MLP),
//   so the graph part is a scatter-add of 96 edge-MLP outputs into acc[n][96].
//
// R7: node unit-mixing moved to tensor cores. 16 nodes per block; the two
//     mixing stages become GEMMs with rows = comp*node (144 rows = 9 m16
//     tiles, each tile one component -> one weight matrix), K=32, N=32,
//     bf16x3 split. Weight B-frags packed once per block; persistent grid.
//     Edge MLP unchanged from R6 (mma bf16x3, register-resident h1/h2).
// ---------------------------------------------------------------------------

#define MAXN 50000
#define PI_F 3.14159265358979323846f
#define CUTOFF_F 5.0f

__device__ float g_acc[(size_t)MAXN * 96];

__device__ __forceinline__ float silu_f(float v) {
    return v * __fdividef(1.0f, 1.0f + __expf(-v));
}
__device__ __forceinline__ uint32_t packbf(float lo, float hi) {
    uint32_t r;
    asm("cvt.rn.bf16x2.f32 %0, %1, %2;" : "=r"(r) : "f"(hi), "f"(lo));
    return r;
}
__device__ __forceinline__ float bf16val(float v) {
    return __bfloat162float(__float2bfloat16(v));
}
__device__ __forceinline__ void pack_hl(float x, float y, uint32_t& h, uint32_t& l) {
    h = packbf(x, y);
    l = packbf(x - bf16val(x), y - bf16val(y));
}
__device__ __forceinline__ void mma_bf16(float c[4], const uint32_t a[4], uint2 b) {
    asm volatile(
        "mma.sync.aligned.m16n8k16.row.col.f32.bf16.bf16.f32 "
        "{%0,%1,%2,%3}, {%4,%5,%6,%7}, {%8,%9}, {%0,%1,%2,%3};"
        : "+f"(c[0]), "+f"(c[1]), "+f"(c[2]), "+f"(c[3])
        : "r"(a[0]), "r"(a[1]), "r"(a[2]), "r"(a[3]), "r"(b.x), "r"(b.y));
}

// ---------------------------------------------------------------------------
// Edge MLP kernel (unchanged from R6). Warp = 16-edge strip.
__global__ void __launch_bounds__(256)
edge_mma_kernel(const float* __restrict__ edge_attr,
                const int*   __restrict__ edge_index,
                const float* __restrict__ edge_weight,
                const float* __restrict__ W1, const float* __restrict__ b1,
                const float* __restrict__ W2, const float* __restrict__ b2,
                const float* __restrict__ W3, const float* __restrict__ b3,
                int E)
{
    __shared__ uint2 sB1h[8][32],  sB1l[8][32];
    __shared__ uint2 sB2h[16][32], sB2l[16][32];
    __shared__ uint2 sB3h[48][32], sB3l[48][32];
    __shared__ float sb1[32], sb2[64], sb3[96];

    const int tid = threadIdx.x;

    {
        int i = tid;
        int f = i >> 5, l = i & 31;
        int nt = f >> 1, kf = f & 1;
        int n = nt * 8 + (l >> 2), k0 = kf * 16 + ((l & 3) << 1);
        const float* Wr = W1 + n * 32 + k0;
        uint32_t h0, l0, h1, l1;
        pack_hl(Wr[0], Wr[1], h0, l0);
        pack_hl(Wr[8], Wr[9], h1, l1);
        sB1h[f][l] = make_uint2(h0, h1);
        sB1l[f][l] = make_uint2(l0, l1);
    }
    for (int i = tid; i < 512; i += 256) {
        int f = i >> 5, l = i & 31;
        int nt = f >> 1, kf = f & 1;
        int n = nt * 8 + (l >> 2), k0 = kf * 16 + ((l & 3) << 1);
        const float* Wr = W2 + n * 32 + k0;
        uint32_t h0, l0, h1, l1;
        pack_hl(Wr[0], Wr[1], h0, l0);
        pack_hl(Wr[8], Wr[9], h1, l1);
        sB2h[f][l] = make_uint2(h0, h1);
        sB2l[f][l] = make_uint2(l0, l1);
    }
    for (int i = tid; i < 1536; i += 256) {
        int f = i >> 5, l = i & 31;
        int nt = f >> 2, kf = f & 3;
        int n = nt * 8 + (l >> 2), k0 = kf * 16 + ((l & 3) << 1);
        const float* Wr = W3 + n * 64 + k0;
        uint32_t h0, l0, h1, l1;
        pack_hl(Wr[0], Wr[1], h0, l0);
        pack_hl(Wr[8], Wr[9], h1, l1);
        sB3h[f][l] = make_uint2(h0, h1);
        sB3l[f][l] = make_uint2(l0, l1);
    }
    if (tid < 32) sb1[tid] = b1[tid];
    if (tid < 64) sb2[tid] = b2[tid];
    if (tid < 96) sb3[tid] = b3[tid];
    __syncthreads();

    const int wid = tid >> 5, lane = tid & 31;
    const int r1 = lane >> 2;
    const int q  = (lane & 3) << 1;
    const int nStrips = (E + 15) >> 4;

    for (int strip = blockIdx.x * 8 + wid; strip < nStrips;
         strip += gridDim.x * 8) {
        int e0 = strip << 4;
        int eA = e0 + r1, eB = eA + 8;
        int eAc = min(eA, E - 1), eBc = min(eB, E - 1);

        uint32_t A1h[2][4], A1l[2][4];
        #pragma unroll
        for (int kf = 0; kf < 2; kf++) {
            const float* pa = edge_attr + (size_t)eAc * 32 + kf * 16 + q;
            const float* pb = edge_attr + (size_t)eBc * 32 + kf * 16 + q;
            float2 v0 = *(const float2*)pa;
            float2 v1 = *(const float2*)pb;
            float2 v2 = *(const float2*)(pa + 8);
            float2 v3 = *(const float2*)(pb + 8);
            pack_hl(v0.x, v0.y, A1h[kf][0], A1l[kf][0]);
            pack_hl(v1.x, v1.y, A1h[kf][1], A1l[kf][1]);
            pack_hl(v2.x, v2.y, A1h[kf][2], A1l[kf][2]);
            pack_hl(v3.x, v3.y, A1h[kf][3], A1l[kf][3]);
        }

        float D1[4][4];
        #pragma unroll
        for (int nt = 0; nt < 4; nt++) {
            float bb0 = sb1[nt * 8 + q], bb1 = sb1[nt * 8 + q + 1];
            D1[nt][0] = bb0; D1[nt][1] = bb1; D1[nt][2] = bb0; D1[nt][3] = bb1;
            #pragma unroll
            for (int kf = 0; kf < 2; kf++) {
                uint2 Bh = sB1h[nt * 2 + kf][lane];
                uint2 Bl = sB1l[nt * 2 + kf][lane];
                mma_bf16(D1[nt], A1h[kf], Bh);
                mma_bf16(D1[nt], A1l[kf], Bh);
                mma_bf16(D1[nt], A1h[kf], Bl);
            }
        }

        uint32_t A2h[2][4], A2l[2][4];
        #pragma unroll
        for (int kf = 0; kf < 2; kf++) {
            int na = 2 * kf, nb = 2 * kf + 1;
            float sa0 = silu_f(D1[na][0]), sa1 = silu_f(D1[na][1]);
            float sa2 = silu_f(D1[na][2]), sa3 = silu_f(D1[na][3]);
            float sb0 = silu_f(D1[nb][0]), sb1v = silu_f(D1[nb][1]);
            float sb2v = silu_f(D1[nb][2]), sb3v = silu_f(D1[nb][3]);
            pack_hl(sa0, sa1, A2h[kf][0], A2l[kf][0]);
            pack_hl(sa2, sa3, A2h[kf][1], A2l[kf][1]);
            pack_hl(sb0, sb1v, A2h[kf][2], A2l[kf][2]);
            pack_hl(sb2v, sb3v, A2h[kf][3], A2l[kf][3]);
        }

        float D2[8][4];
        #pragma unroll
        for (int nt = 0; nt < 8; nt++) {
            float bb0 = sb2[nt * 8 + q], bb1 = sb2[nt * 8 + q + 1];
            D2[nt][0] = bb0; D2[nt][1] = bb1; D2[nt][2] = bb0; D2[nt][3] = bb1;
            #pragma unroll
            for (int kf = 0; kf < 2; kf++) {
                uint2 Bh = sB2h[nt * 2 + kf][lane];
                uint2 Bl = sB2l[nt * 2 + kf][lane];
                mma_bf16(D2[nt], A2h[kf], Bh);
                mma_bf16(D2[nt], A2l[kf], Bh);
                mma_bf16(D2[nt], A2h[kf], Bl);
            }
        }

        uint32_t A3h[4][4], A3l[4][4];
        #pragma unroll
        for (int kf = 0; kf < 4; kf++) {
            int na = 2 * kf, nb = 2 * kf + 1;
            float sa0 = silu_f(D2[na][0]), sa1 = silu_f(D2[na][1]);
            float sa2 = silu_f(D2[na][2]), sa3 = silu_f(D2[na][3]);
            float sb0 = silu_f(D2[nb][0]), sb1v = silu_f(D2[nb][1]);
            float sb2v = silu_f(D2[nb][2]), sb3v = silu_f(D2[nb][3]);
            pack_hl(sa0, sa1, A3h[kf][0], A3l[kf][0]);
            pack_hl(sa2, sa3, A3h[kf][1], A3l[kf][1]);
            pack_hl(sb0, sb1v, A3h[kf][2], A3l[kf][2]);
            pack_hl(sb2v, sb3v, A3h[kf][3], A3l[kf][3]);
        }

        float D3[12][4];
        #pragma unroll
        for (int nt = 0; nt < 12; nt++) {
            float bb0 = sb3[nt * 8 + q], bb1 = sb3[nt * 8 + q + 1];
            D3[nt][0] = bb0; D3[nt][1] = bb1; D3[nt][2] = bb0; D3[nt][3] = bb1;
            #pragma unroll
            for (int kf = 0; kf < 4; kf++) {
                uint2 Bh = sB3h[nt * 4 + kf][lane];
                uint2 Bl = sB3l[nt * 4 + kf][lane];
                mma_bf16(D3[nt], A3h[kf], Bh);
                mma_bf16(D3[nt], A3l[kf], Bh);
                mma_bf16(D3[nt], A3h[kf], Bl);
            }
        }

        float wA = edge_weight[eAc], wB = edge_weight[eBc];
        float CcA = (wA < CUTOFF_F)
                  ? 0.5f * (__cosf(wA * (PI_F / CUTOFF_F)) + 1.0f) : 0.0f;
        float CcB = (wB < CUTOFF_F)
                  ? 0.5f * (__cosf(wB * (PI_F / CUTOFF_F)) + 1.0f) : 0.0f;
        int dA = edge_index[E + eAc], dB = edge_index[E + eBc];
        bool okA = eA < E, okB = eB < E;
        float* gA = g_acc + (size_t)dA * 96 + q;
        float* gB = g_acc + (size_t)dB * 96 + q;

        #pragma unroll
        for (int nt = 0; nt < 12; nt++) {
            if (okA) {
                float t0 = silu_f(D3[nt][0]) * CcA;
                float t1 = silu_f(D3[nt][1]) * CcA;
                asm volatile("red.global.add.v2.f32 [%0], {%1, %2};"
                             :: "l"(gA + nt * 8), "f"(t0), "f"(t1) : "memory");
            }
            if (okB) {
                float t2 = silu_f(D3[nt][2]) * CcB;
                float t3 = silu_f(D3[nt][3]) * CcB;
                asm volatile("red.global.add.v2.f32 [%0], {%1, %2};"
                             :: "l"(gB + nt * 8), "f"(t2), "f"(t3) : "memory");
            }
        }
    }
}

// ---------------------------------------------------------------------------
// Node kernel, MMA mixing. Block = 256 threads = 16 nodes per strip.
// Rows of the mixing GEMMs: row = comp*16 + localNode (144 rows, 9 m16
// tiles; tile rt -> weight matrix 0 (rt==0), 1 (rt 1..3), 2 (rt 4..8)).
#define RS 36   // c_sm / r_sm row stride in floats (even -> 8B aligned)

__global__ void __launch_bounds__(256)
node_mma_kernel(const float* __restrict__ X,
                const float* __restrict__ Wt,
                float* __restrict__ out,
                int nNodes, int nStrips)
{
    extern __shared__ char smem[];
    uint2* sBh  = (uint2*)smem;                        // [mat*256 + f*32 + l], 6*8*32
    uint2* sBl  = (uint2*)(smem + 12288);
    float* c_sm = (float*)(smem + 24576);              // [144][RS]
    float* r_sm = (float*)(smem + 24576 + 144 * RS * 4);

    const int tid  = threadIdx.x;
    const int lane = tid & 31, wid = tid >> 5;
    const int gr   = lane >> 2, tig = lane & 3;

    // ---- pack the 6 mixing matrices into B-fragment layout (once) ----
    for (int i = tid; i < 1536; i += 256) {
        int mat = i >> 8, rem = i & 255;
        int f = rem >> 5, l = rem & 31;
        int nt = f >> 1, kf = f & 1;
        int n = nt * 8 + (l >> 2), k0 = kf * 16 + ((l & 3) << 1);
        const float* Wr = Wt + mat * 1024 + n * 32 + k0;
        uint32_t h0, l0, h1, l1;
        pack_hl(Wr[0], Wr[1], h0, l0);
        pack_hl(Wr[8], Wr[9], h1, l1);
        sBh[i] = make_uint2(h0, h1);
        sBl[i] = make_uint2(l0, l1);
    }
    __syncthreads();

    const int nl0 = tid >> 5;      // local node of cell0 (0..7); cell1: +8
    const int u   = lane;          // unit

    for (int s = blockIdx.x; s < nStrips; s += gridDim.x) {
        const int nodeBase = s << 4;
        float Xn[2][9];

        // ---------- EW-A: normalize + decompose -> c_sm ----------
        #pragma unroll
        for (int cc = 0; cc < 2; cc++) {
            int r0 = nl0 + cc * 8;
            int n  = nodeBase + r0;
            int nc = min(n, nNodes - 1);
            float nrm = 1.0f;
            #pragma unroll
            for (int t = 0; t < 9; t++) {
                float v = X[((size_t)nc * 9 + t) * 32 + u];
                Xn[cc][t] = v; nrm += v * v;
            }
            float inv = __fdividef(1.0f, nrm);
            #pragma unroll
            for (int t = 0; t < 9; t++) Xn[cc][t] *= inv;

            const float* x = Xn[cc];
            float tr3 = (x[0] + x[4] + x[8]) * (1.0f / 3.0f);
            float* cp = c_sm + r0 * RS + u;           // row t*16+r0
            cp[0 * 16 * RS] = tr3;
            cp[1 * 16 * RS] = 0.5f * (x[1] - x[3]);
            cp[2 * 16 * RS] = 0.5f * (x[2] - x[6]);
            cp[3 * 16 * RS] = 0.5f * (x[5] - x[7]);
            cp[4 * 16 * RS] = x[0] - tr3;
            cp[5 * 16 * RS] = 0.5f * (x[1] + x[3]);
            cp[6 * 16 * RS] = 0.5f * (x[2] + x[6]);
            cp[7 * 16 * RS] = x[4] - tr3;
            cp[8 * 16 * RS] = 0.5f * (x[5] + x[7]);
        }
        __syncthreads();

        // ---------- GEMM stage 1 (mats 0..2) ----------
        #pragma unroll 1
        for (int t5 = wid; t5 < 36; t5 += 8) {
            int rt = t5 >> 2, nt = t5 & 3;
            int mat = (rt == 0) ? 0 : (rt < 4) ? 1 : 2;
            uint32_t Ah[2][4], Al[2][4];
            const float* crow0 = c_sm + (16 * rt + gr) * RS;
            const float* crow1 = crow0 + 8 * RS;
            #pragma unroll
            for (int kf = 0; kf < 2; kf++) {
                int c0 = kf * 16 + 2 * tig;
                float2 v0 = *(const float2*)(crow0 + c0);
                float2 v1 = *(const float2*)(crow1 + c0);
                float2 v2 = *(const float2*)(crow0 + c0 + 8);
                float2 v3 = *(const float2*)(crow1 + c0 + 8);
                pack_hl(v0.x, v0.y, Ah[kf][0], Al[kf][0]);
                pack_hl(v1.x, v1.y, Ah[kf][1], Al[kf][1]);
                pack_hl(v2.x, v2.y, Ah[kf][2], Al[kf][2]);
                pack_hl(v3.x, v3.y, Ah[kf][3], Al[kf][3]);
            }
            float D[4] = {0.f, 0.f, 0.f, 0.f};
            #pragma unroll
            for (int kf = 0; kf < 2; kf++) {
                uint2 Bh = sBh[mat * 256 + (nt * 2 + kf) * 32 + lane];
                uint2 Bl = sBl[mat * 256 + (nt * 2 + kf) * 32 + lane];
                mma_bf16(D, Ah[kf], Bh);
                mma_bf16(D, Al[kf], Bh);
                mma_bf16(D, Ah[kf], Bl);
            }
            float* rrow = r_sm + (16 * rt + gr) * RS + nt * 8 + 2 * tig;
            *(float2*)rrow = make_float2(D[0], D[1]);
            *(float2*)(rrow + 8 * RS) = make_float2(D[2], D[3]);
        }
        __syncthreads();

        // ---------- EW-B: msg combine, M = YG+GY, renorm -> c_sm ----------
        #pragma unroll
        for (int cc = 0; cc < 2; cc++) {
            int r0 = nl0 + cc * 8;
            int n  = nodeBase + r0;
            const float* rp = r_sm + r0 * RS + u;
            float Ip  = rp[0 * 16 * RS];
            float a01 = rp[1 * 16 * RS];
            float a02 = rp[2 * 16 * RS];
            float a12 = rp[3 * 16 * RS];
            float s00 = rp[4 * 16 * RS];
            float s01 = rp[5 * 16 * RS];
            float s02 = rp[6 * 16 * RS];
            float s11 = rp[7 * 16 * RS];
            float s12 = rp[8 * 16 * RS];
            float s22 = -(s00 + s11);

            float sI = 0.f, sA = 0.f, sS = 0.f;
            if (n < nNodes) {
                float* ap = g_acc + (size_t)n * 96 + u * 3;
                sI = ap[0]; sA = ap[1]; sS = ap[2];
                ap[0] = 0.f; ap[1] = 0.f; ap[2] = 0.f;   // re-zero
            }

            float Y[9], G[9];
            Y[0] = Ip + s00;  Y[1] = a01 + s01;  Y[2] = a02 + s02;
            Y[3] = s01 - a01; Y[4] = Ip + s11;   Y[5] = a12 + s12;
            Y[6] = s02 - a02; Y[7] = s12 - a12;  Y[8] = Ip + s22;
            G[0] = Ip*sI + s00*sS;  G[1] = a01*sA + s01*sS;  G[2] = a02*sA + s02*sS;
            G[3] = s01*sS - a01*sA; G[4] = Ip*sI + s11*sS;   G[5] = a12*sA + s12*sS;
            G[6] = s02*sS - a02*sA; G[7] = s12*sS - a12*sA;  G[8] = Ip*sI + s22*sS;

            float M[9];
            #pragma unroll
            for (int i = 0; i < 3; i++)
                #pragma unroll
                for (int l = 0; l < 3; l++) {
                    float a2 = 0.0f;
                    #pragma unroll
                    for (int j = 0; j < 3; j++)
                        a2 += Y[i*3+j] * G[j*3+l] + G[i*3+j] * Y[j*3+l];
                    M[i*3+l] = a2;
                }

            float np = 1.0f;
            #pragma unroll
            for (int t = 0; t < 9; t++) np += M[t] * M[t];
            float inv2 = __fdividef(1.0f, np);
            float trm = (M[0] + M[4] + M[8]) * (1.0f / 3.0f);

            float* cp = c_sm + r0 * RS + u;
            cp[0 * 16 * RS] = trm * inv2;
            cp[1 * 16 * RS] = 0.5f * (M[1] - M[3]) * inv2;
            cp[2 * 16 * RS] = 0.5f * (M[2] - M[6]) * inv2;
            cp[3 * 16 * RS] = 0.5f * (M[5] - M[7]) * inv2;
            cp[4 * 16 * RS] = (M[0] - trm) * inv2;
            cp[5 * 16 * RS] = 0.5f * (M[1] + M[3]) * inv2;
            cp[6 * 16 * RS] = 0.5f * (M[2] + M[6]) * inv2;
            cp[7 * 16 * RS] = (M[4] - trm) * inv2;
            cp[8 * 16 * RS] = 0.5f * (M[5] + M[7]) * inv2;
        }
        __syncthreads();

        // ---------- GEMM stage 2 (mats 3..5) ----------
        #pragma unroll 1
        for (int t5 = wid; t5 < 36; t5 += 8) {
            int rt = t5 >> 2, nt = t5 & 3;
            int mat = 3 + ((rt == 0) ? 0 : (rt < 4) ? 1 : 2);
            uint32_t Ah[2][4], Al[2][4];
            const float* crow0 = c_sm + (16 * rt + gr) * RS;
            const float* crow1 = crow0 + 8 * RS;
            #pragma unroll
            for (int kf = 0; kf < 2; kf++) {
                int c0 = kf * 16 + 2 * tig;
                float2 v0 = *(const float2*)(crow0 + c0);
                float2 v1 = *(const float2*)(crow1 + c0);
                float2 v2 = *(const float2*)(crow0 + c0 + 8);
                float2 v3 = *(const float2*)(crow1 + c0 + 8);
                pack_hl(v0.x, v0.y, Ah[kf][0], Al[kf][0]);
                pack_hl(v1.x, v1.y, Ah[kf][1], Al[kf][1]);
                pack_hl(v2.x, v2.y, Ah[kf][2], Al[kf][2]);
                pack_hl(v3.x, v3.y, Ah[kf][3], Al[kf][3]);
            }
            float D[4] = {0.f, 0.f, 0.f, 0.f};
            #pragma unroll
            for (int kf = 0; kf < 2; kf++) {
                uint2 Bh = sBh[mat * 256 + (nt * 2 + kf) * 32 + lane];
                uint2 Bl = sBl[mat * 256 + (nt * 2 + kf) * 32 + lane];
                mma_bf16(D, Ah[kf], Bh);
                mma_bf16(D, Al[kf], Bh);
                mma_bf16(D, Ah[kf], Bl);
            }
            float* rrow = r_sm + (16 * rt + gr) * RS + nt * 8 + 2 * tig;
            *(float2*)rrow = make_float2(D[0], D[1]);
            *(float2*)(rrow + 8 * RS) = make_float2(D[2], D[3]);
        }
        __syncthreads();

        // ---------- EW-C: D, out = Xn + D + D@D ----------
        #pragma unroll
        for (int cc = 0; cc < 2; cc++) {
            int r0 = nl0 + cc * 8;
            int n  = nodeBase + r0;
            const float* rp = r_sm + r0 * RS + u;
            float Ip2 = rp[0 * 16 * RS];
            float b01 = rp[1 * 16 * RS];
            float b02 = rp[2 * 16 * RS];
            float b12 = rp[3 * 16 * RS];
            float t00 = rp[4 * 16 * RS];
            float t01 = rp[5 * 16 * RS];
            float t02 = rp[6 * 16 * RS];
            float t11 = rp[7 * 16 * RS];
            float t12 = rp[8 * 16 * RS];
            float t22 = -(t00 + t11);

            float D[9];
            D[0] = Ip2 + t00;  D[1] = b01 + t01;  D[2] = b02 + t02;
            D[3] = t01 - b01;  D[4] = Ip2 + t11;  D[5] = b12 + t12;
            D[6] = t02 - b02;  D[7] = t12 - b12;  D[8] = Ip2 + t22;

            if (n < nNodes) {
                #pragma unroll
                for (int i = 0; i < 3; i++)
                    #pragma unroll
                    for (int l = 0; l < 3; l++) {
                        float o = Xn[cc][i*3+l] + D[i*3+l];
                        #pragma unroll
                        for (int j = 0; j < 3; j++)
                            o += D[i*3+j] * D[j*3+l];
                        out[((size_t)n * 9 + (i*3+l)) * 32 + u] = o;
                    }
            }
        }
        __syncthreads();   // protect c_sm/r_sm before next strip
    }
}

// ---------------------------------------------------------------------------
extern "C" void kernel_launch(void* const* d_in, const int* in_sizes, int n_in,
                              void* d_out, int out_size)
{
    const float* X           = (const float*)d_in[0];
    const int*   edge_index  = (const int*)  d_in[1];
    const float* edge_weight = (const float*)d_in[2];
    const float* edge_attr   = (const float*)d_in[3];
    const float* W1 = (const float*)d_in[4];
    const float* b1 = (const float*)d_in[5];
    const float* W2 = (const float*)d_in[6];
    const float* b2 = (const float*)d_in[7];
    const float* W3 = (const float*)d_in[8];
    const float* b3 = (const float*)d_in[9];
    const float* Wt = (const float*)d_in[10];
    float* out = (float*)d_out;

    int N = in_sizes[0] / 288;   // X is (N,3,3,32)
    if (N > MAXN) N = MAXN;
    int E = in_sizes[2];         // edge_weight is (E,)

    int nStrips = (E + 15) >> 4;
    int grid = (nStrips + 7) / 8;
    if (grid > 296) grid = 296;

    edge_mma_kernel<<<grid, 256>>>(
        edge_attr, edge_index, edge_weight, W1, b1, W2, b2, W3, b3, E);

    // Node kernel: dynamic smem = B-frags (24576) + c_sm + r_sm.
    int nodeSmem = 24576 + 2 * 144 * RS * 4;   // 66048 bytes
    static bool attr_set = false;
    if (!attr_set) {
        cudaFuncSetAttribute(node_mma_kernel,
                             cudaFuncAttributeMaxDynamicSharedMemorySize, nodeSmem);
        attr_set = true;
    }
    int nodeStrips = (N + 15) / 16;
    int nodeGrid = nodeStrips < 444 ? nodeStrips : 444;
    node_mma_kernel<<<nodeGrid, 256, nodeSmem>>>(X, Wt, out, N, nodeStrips);
}

// round 8
// speedup vs baseline: 4.1738x; 1.1522x over previous
#include <cuda_runtime.h>
#include <cuda_bf16.h>
#include <cstdint>

// ---------------------------------------------------------------------------
// TensorNet interaction.
//   msg[n] = (component tensors of n) * (per-node scalar sums of edge MLP),
//   so the graph part is a scatter-add of 96 edge-MLP outputs into acc[n][96].
//
// R8: node kernel GEMM phase restructured: one warp per m16 row-tile (rt),
//     A-fragments loaded/split ONCE per rt and reused for all 4 n-tiles
//     (was: per (rt,nt) -> 4x redundant LDS+pack ALU). Row ownership is
//     warp-exclusive, so components and results share ONE in-place SMEM
//     buffer -> smem 66KB -> 45KB -> 4 CTAs/SM (occ 35% -> ~50%).
//     Edge MLP unchanged (mma bf16x3, register-resident h1/h2).
// ---------------------------------------------------------------------------

#define MAXN 50000
#define PI_F 3.14159265358979323846f
#define CUTOFF_F 5.0f

__device__ float g_acc[(size_t)MAXN * 96];

__device__ __forceinline__ float silu_f(float v) {
    return v * __fdividef(1.0f, 1.0f + __expf(-v));
}
__device__ __forceinline__ uint32_t packbf(float lo, float hi) {
    uint32_t r;
    asm("cvt.rn.bf16x2.f32 %0, %1, %2;" : "=r"(r) : "f"(hi), "f"(lo));
    return r;
}
__device__ __forceinline__ float bf16val(float v) {
    return __bfloat162float(__float2bfloat16(v));
}
__device__ __forceinline__ void pack_hl(float x, float y, uint32_t& h, uint32_t& l) {
    h = packbf(x, y);
    l = packbf(x - bf16val(x), y - bf16val(y));
}
__device__ __forceinline__ void mma_bf16(float c[4], const uint32_t a[4], uint2 b) {
    asm volatile(
        "mma.sync.aligned.m16n8k16.row.col.f32.bf16.bf16.f32 "
        "{%0,%1,%2,%3}, {%4,%5,%6,%7}, {%8,%9}, {%0,%1,%2,%3};"
        : "+f"(c[0]), "+f"(c[1]), "+f"(c[2]), "+f"(c[3])
        : "r"(a[0]), "r"(a[1]), "r"(a[2]), "r"(a[3]), "r"(b.x), "r"(b.y));
}

// ---------------------------------------------------------------------------
// Edge MLP kernel (unchanged). Warp = 16-edge strip.
__global__ void __launch_bounds__(256)
edge_mma_kernel(const float* __restrict__ edge_attr,
                const int*   __restrict__ edge_index,
                const float* __restrict__ edge_weight,
                const float* __restrict__ W1, const float* __restrict__ b1,
                const float* __restrict__ W2, const float* __restrict__ b2,
                const float* __restrict__ W3, const float* __restrict__ b3,
                int E)
{
    __shared__ uint2 sB1h[8][32],  sB1l[8][32];
    __shared__ uint2 sB2h[16][32], sB2l[16][32];
    __shared__ uint2 sB3h[48][32], sB3l[48][32];
    __shared__ float sb1[32], sb2[64], sb3[96];

    const int tid = threadIdx.x;

    {
        int i = tid;
        int f = i >> 5, l = i & 31;
        int nt = f >> 1, kf = f & 1;
        int n = nt * 8 + (l >> 2), k0 = kf * 16 + ((l & 3) << 1);
        const float* Wr = W1 + n * 32 + k0;
        uint32_t h0, l0, h1, l1;
        pack_hl(Wr[0], Wr[1], h0, l0);
        pack_hl(Wr[8], Wr[9], h1, l1);
        sB1h[f][l] = make_uint2(h0, h1);
        sB1l[f][l] = make_uint2(l0, l1);
    }
    for (int i = tid; i < 512; i += 256) {
        int f = i >> 5, l = i & 31;
        int nt = f >> 1, kf = f & 1;
        int n = nt * 8 + (l >> 2), k0 = kf * 16 + ((l & 3) << 1);
        const float* Wr = W2 + n * 32 + k0;
        uint32_t h0, l0, h1, l1;
        pack_hl(Wr[0], Wr[1], h0, l0);
        pack_hl(Wr[8], Wr[9], h1, l1);
        sB2h[f][l] = make_uint2(h0, h1);
        sB2l[f][l] = make_uint2(l0, l1);
    }
    for (int i = tid; i < 1536; i += 256) {
        int f = i >> 5, l = i & 31;
        int nt = f >> 2, kf = f & 3;
        int n = nt * 8 + (l >> 2), k0 = kf * 16 + ((l & 3) << 1);
        const float* Wr = W3 + n * 64 + k0;
        uint32_t h0, l0, h1, l1;
        pack_hl(Wr[0], Wr[1], h0, l0);
        pack_hl(Wr[8], Wr[9], h1, l1);
        sB3h[f][l] = make_uint2(h0, h1);
        sB3l[f][l] = make_uint2(l0, l1);
    }
    if (tid < 32) sb1[tid] = b1[tid];
    if (tid < 64) sb2[tid] = b2[tid];
    if (tid < 96) sb3[tid] = b3[tid];
    __syncthreads();

    const int wid = tid >> 5, lane = tid & 31;
    const int r1 = lane >> 2;
    const int q  = (lane & 3) << 1;
    const int nStrips = (E + 15) >> 4;

    for (int strip = blockIdx.x * 8 + wid; strip < nStrips;
         strip += gridDim.x * 8) {
        int e0 = strip << 4;
        int eA = e0 + r1, eB = eA + 8;
        int eAc = min(eA, E - 1), eBc = min(eB, E - 1);

        uint32_t A1h[2][4], A1l[2][4];
        #pragma unroll
        for (int kf = 0; kf < 2; kf++) {
            const float* pa = edge_attr + (size_t)eAc * 32 + kf * 16 + q;
            const float* pb = edge_attr + (size_t)eBc * 32 + kf * 16 + q;
            float2 v0 = *(const float2*)pa;
            float2 v1 = *(const float2*)pb;
            float2 v2 = *(const float2*)(pa + 8);
            float2 v3 = *(const float2*)(pb + 8);
            pack_hl(v0.x, v0.y, A1h[kf][0], A1l[kf][0]);
            pack_hl(v1.x, v1.y, A1h[kf][1], A1l[kf][1]);
            pack_hl(v2.x, v2.y, A1h[kf][2], A1l[kf][2]);
            pack_hl(v3.x, v3.y, A1h[kf][3], A1l[kf][3]);
        }

        float D1[4][4];
        #pragma unroll
        for (int nt = 0; nt < 4; nt++) {
            float bb0 = sb1[nt * 8 + q], bb1 = sb1[nt * 8 + q + 1];
            D1[nt][0] = bb0; D1[nt][1] = bb1; D1[nt][2] = bb0; D1[nt][3] = bb1;
            #pragma unroll
            for (int kf = 0; kf < 2; kf++) {
                uint2 Bh = sB1h[nt * 2 + kf][lane];
                uint2 Bl = sB1l[nt * 2 + kf][lane];
                mma_bf16(D1[nt], A1h[kf], Bh);
                mma_bf16(D1[nt], A1l[kf], Bh);
                mma_bf16(D1[nt], A1h[kf], Bl);
            }
        }

        uint32_t A2h[2][4], A2l[2][4];
        #pragma unroll
        for (int kf = 0; kf < 2; kf++) {
            int na = 2 * kf, nb = 2 * kf + 1;
            float sa0 = silu_f(D1[na][0]), sa1 = silu_f(D1[na][1]);
            float sa2 = silu_f(D1[na][2]), sa3 = silu_f(D1[na][3]);
            float sb0 = silu_f(D1[nb][0]), sb1v = silu_f(D1[nb][1]);
            float sb2v = silu_f(D1[nb][2]), sb3v = silu_f(D1[nb][3]);
            pack_hl(sa0, sa1, A2h[kf][0], A2l[kf][0]);
            pack_hl(sa2, sa3, A2h[kf][1], A2l[kf][1]);
            pack_hl(sb0, sb1v, A2h[kf][2], A2l[kf][2]);
            pack_hl(sb2v, sb3v, A2h[kf][3], A2l[kf][3]);
        }

        float D2[8][4];
        #pragma unroll
        for (int nt = 0; nt < 8; nt++) {
            float bb0 = sb2[nt * 8 + q], bb1 = sb2[nt * 8 + q + 1];
            D2[nt][0] = bb0; D2[nt][1] = bb1; D2[nt][2] = bb0; D2[nt][3] = bb1;
            #pragma unroll
            for (int kf = 0; kf < 2; kf++) {
                uint2 Bh = sB2h[nt * 2 + kf][lane];
                uint2 Bl = sB2l[nt * 2 + kf][lane];
                mma_bf16(D2[nt], A2h[kf], Bh);
                mma_bf16(D2[nt], A2l[kf], Bh);
                mma_bf16(D2[nt], A2h[kf], Bl);
            }
        }

        uint32_t A3h[4][4], A3l[4][4];
        #pragma unroll
        for (int kf = 0; kf < 4; kf++) {
            int na = 2 * kf, nb = 2 * kf + 1;
            float sa0 = silu_f(D2[na][0]), sa1 = silu_f(D2[na][1]);
            float sa2 = silu_f(D2[na][2]), sa3 = silu_f(D2[na][3]);
            float sb0 = silu_f(D2[nb][0]), sb1v = silu_f(D2[nb][1]);
            float sb2v = silu_f(D2[nb][2]), sb3v = silu_f(D2[nb][3]);
            pack_hl(sa0, sa1, A3h[kf][0], A3l[kf][0]);
            pack_hl(sa2, sa3, A3h[kf][1], A3l[kf][1]);
            pack_hl(sb0, sb1v, A3h[kf][2], A3l[kf][2]);
            pack_hl(sb2v, sb3v, A3h[kf][3], A3l[kf][3]);
        }

        float D3[12][4];
        #pragma unroll
        for (int nt = 0; nt < 12; nt++) {
            float bb0 = sb3[nt * 8 + q], bb1 = sb3[nt * 8 + q + 1];
            D3[nt][0] = bb0; D3[nt][1] = bb1; D3[nt][2] = bb0; D3[nt][3] = bb1;
            #pragma unroll
            for (int kf = 0; kf < 4; kf++) {
                uint2 Bh = sB3h[nt * 4 + kf][lane];
                uint2 Bl = sB3l[nt * 4 + kf][lane];
                mma_bf16(D3[nt], A3h[kf], Bh);
                mma_bf16(D3[nt], A3l[kf], Bh);
                mma_bf16(D3[nt], A3h[kf], Bl);
            }
        }

        float wA = edge_weight[eAc], wB = edge_weight[eBc];
        float CcA = (wA < CUTOFF_F)
                  ? 0.5f * (__cosf(wA * (PI_F / CUTOFF_F)) + 1.0f) : 0.0f;
        float CcB = (wB < CUTOFF_F)
                  ? 0.5f * (__cosf(wB * (PI_F / CUTOFF_F)) + 1.0f) : 0.0f;
        int dA = edge_index[E + eAc], dB = edge_index[E + eBc];
        bool okA = eA < E, okB = eB < E;
        float* gA = g_acc + (size_t)dA * 96 + q;
        float* gB = g_acc + (size_t)dB * 96 + q;

        #pragma unroll
        for (int nt = 0; nt < 12; nt++) {
            if (okA) {
                float t0 = silu_f(D3[nt][0]) * CcA;
                float t1 = silu_f(D3[nt][1]) * CcA;
                asm volatile("red.global.add.v2.f32 [%0], {%1, %2};"
                             :: "l"(gA + nt * 8), "f"(t0), "f"(t1) : "memory");
            }
            if (okB) {
                float t2 = silu_f(D3[nt][2]) * CcB;
                float t3 = silu_f(D3[nt][3]) * CcB;
                asm volatile("red.global.add.v2.f32 [%0], {%1, %2};"
                             :: "l"(gB + nt * 8), "f"(t2), "f"(t3) : "memory");
            }
        }
    }
}

// ---------------------------------------------------------------------------
// Node kernel, MMA mixing, in-place c/r buffer.
// Rows: row = comp*16 + localNode (144 rows, 9 m16 tiles).
// GEMM: one warp per row-tile rt (warp 0 also takes rt 8); A-frags loaded
// once per rt, all 4 n-tiles computed, then results written IN PLACE into
// the same rows (safe: rows are warp-exclusive; mma.sync orders rd<wr).
#define RS 36   // row stride in floats (even -> 8B aligned float2)

__global__ void __launch_bounds__(256)
node_mma_kernel(const float* __restrict__ X,
                const float* __restrict__ Wt,
                float* __restrict__ out,
                int nNodes, int nStrips)
{
    extern __shared__ char smem[];
    uint2* sBh  = (uint2*)smem;                       // [mat*256 + f*32 + l]
    uint2* sBl  = (uint2*)(smem + 12288);
    float* cr   = (float*)(smem + 24576);             // [144][RS], comps AND results

    const int tid  = threadIdx.x;
    const int lane = tid & 31, wid = tid >> 5;
    const int gr   = lane >> 2, tig = lane & 3;

    for (int i = tid; i < 1536; i += 256) {
        int mat = i >> 8, rem = i & 255;
        int f = rem >> 5, l = rem & 31;
        int nt = f >> 1, kf = f & 1;
        int n = nt * 8 + (l >> 2), k0 = kf * 16 + ((l & 3) << 1);
        const float* Wr = Wt + mat * 1024 + n * 32 + k0;
        uint32_t h0, l0, h1, l1;
        pack_hl(Wr[0], Wr[1], h0, l0);
        pack_hl(Wr[8], Wr[9], h1, l1);
        sBh[i] = make_uint2(h0, h1);
        sBl[i] = make_uint2(l0, l1);
    }
    __syncthreads();

    const int nl0 = tid >> 5;      // local node of cell0 (0..7); cell1: +8
    const int u   = lane;          // unit

    for (int s = blockIdx.x; s < nStrips; s += gridDim.x) {
        const int nodeBase = s << 4;
        float Xn[2][9];

        // ---------- EW-A: normalize + decompose -> cr ----------
        #pragma unroll
        for (int cc = 0; cc < 2; cc++) {
            int r0 = nl0 + cc * 8;
            int n  = nodeBase + r0;
            int nc = min(n, nNodes - 1);
            float nrm = 1.0f;
            #pragma unroll
            for (int t = 0; t < 9; t++) {
                float v = X[((size_t)nc * 9 + t) * 32 + u];
                Xn[cc][t] = v; nrm += v * v;
            }
            float inv = __fdividef(1.0f, nrm);
            #pragma unroll
            for (int t = 0; t < 9; t++) Xn[cc][t] *= inv;

            const float* x = Xn[cc];
            float tr3 = (x[0] + x[4] + x[8]) * (1.0f / 3.0f);
            float* cp = cr + r0 * RS + u;
            cp[0 * 16 * RS] = tr3;
            cp[1 * 16 * RS] = 0.5f * (x[1] - x[3]);
            cp[2 * 16 * RS] = 0.5f * (x[2] - x[6]);
            cp[3 * 16 * RS] = 0.5f * (x[5] - x[7]);
            cp[4 * 16 * RS] = x[0] - tr3;
            cp[5 * 16 * RS] = 0.5f * (x[1] + x[3]);
            cp[6 * 16 * RS] = 0.5f * (x[2] + x[6]);
            cp[7 * 16 * RS] = x[4] - tr3;
            cp[8 * 16 * RS] = 0.5f * (x[5] + x[7]);
        }
        __syncthreads();

        // ---------- GEMM stage 1 (mats 0..2), warp per rt, in-place ----------
        #pragma unroll 1
        for (int rt = wid; rt < 9; rt += 8) {
            int mat = (rt == 0) ? 0 : (rt < 4) ? 1 : 2;
            const float* crow0 = cr + (16 * rt + gr) * RS;
            const float* crow1 = crow0 + 8 * RS;
            uint32_t Ah[2][4], Al[2][4];
            #pragma unroll
            for (int kf = 0; kf < 2; kf++) {
                int c0 = kf * 16 + 2 * tig;
                float2 v0 = *(const float2*)(crow0 + c0);
                float2 v1 = *(const float2*)(crow1 + c0);
                float2 v2 = *(const float2*)(crow0 + c0 + 8);
                float2 v3 = *(const float2*)(crow1 + c0 + 8);
                pack_hl(v0.x, v0.y, Ah[kf][0], Al[kf][0]);
                pack_hl(v1.x, v1.y, Ah[kf][1], Al[kf][1]);
                pack_hl(v2.x, v2.y, Ah[kf][2], Al[kf][2]);
                pack_hl(v3.x, v3.y, Ah[kf][3], Al[kf][3]);
            }
            float D[4][4];
            #pragma unroll
            for (int nt = 0; nt < 4; nt++) {
                D[nt][0] = 0.f; D[nt][1] = 0.f; D[nt][2] = 0.f; D[nt][3] = 0.f;
                #pragma unroll
                for (int kf = 0; kf < 2; kf++) {
                    uint2 Bh = sBh[mat * 256 + (nt * 2 + kf) * 32 + lane];
                    uint2 Bl = sBl[mat * 256 + (nt * 2 + kf) * 32 + lane];
                    mma_bf16(D[nt], Ah[kf], Bh);
                    mma_bf16(D[nt], Al[kf], Bh);
                    mma_bf16(D[nt], Ah[kf], Bl);
                }
            }
            float* wr0 = cr + (16 * rt + gr) * RS + 2 * tig;
            float* wr1 = wr0 + 8 * RS;
            #pragma unroll
            for (int nt = 0; nt < 4; nt++) {
                *(float2*)(wr0 + nt * 8) = make_float2(D[nt][0], D[nt][1]);
                *(float2*)(wr1 + nt * 8) = make_float2(D[nt][2], D[nt][3]);
            }
        }
        __syncthreads();

        // ---------- EW-B: msg combine, M = YG+GY, renorm -> cr (in place) ----------
        #pragma unroll
        for (int cc = 0; cc < 2; cc++) {
            int r0 = nl0 + cc * 8;
            int n  = nodeBase + r0;
            float* rp = cr + r0 * RS + u;
            float Ip  = rp[0 * 16 * RS];
            float a01 = rp[1 * 16 * RS];
            float a02 = rp[2 * 16 * RS];
            float a12 = rp[3 * 16 * RS];
            float s00 = rp[4 * 16 * RS];
            float s01 = rp[5 * 16 * RS];
            float s02 = rp[6 * 16 * RS];
            float s11 = rp[7 * 16 * RS];
            float s12 = rp[8 * 16 * RS];
            float s22 = -(s00 + s11);

            float sI = 0.f, sA = 0.f, sS = 0.f;
            if (n < nNodes) {
                float* ap = g_acc + (size_t)n * 96 + u * 3;
                sI = ap[0]; sA = ap[1]; sS = ap[2];
                ap[0] = 0.f; ap[1] = 0.f; ap[2] = 0.f;   // re-zero
            }

            float Y[9], G[9];
            Y[0] = Ip + s00;  Y[1] = a01 + s01;  Y[2] = a02 + s02;
            Y[3] = s01 - a01; Y[4] = Ip + s11;   Y[5] = a12 + s12;
            Y[6] = s02 - a02; Y[7] = s12 - a12;  Y[8] = Ip + s22;
            G[0] = Ip*sI + s00*sS;  G[1] = a01*sA + s01*sS;  G[2] = a02*sA + s02*sS;
            G[3] = s01*sS - a01*sA; G[4] = Ip*sI + s11*sS;   G[5] = a12*sA + s12*sS;
            G[6] = s02*sS - a02*sA; G[7] = s12*sS - a12*sA;  G[8] = Ip*sI + s22*sS;

            float M[9];
            #pragma unroll
            for (int i = 0; i < 3; i++)
                #pragma unroll
                for (int l = 0; l < 3; l++) {
                    float a2 = 0.0f;
                    #pragma unroll
                    for (int j = 0; j < 3; j++)
                        a2 += Y[i*3+j] * G[j*3+l] + G[i*3+j] * Y[j*3+l];
                    M[i*3+l] = a2;
                }

            float np = 1.0f;
            #pragma unroll
            for (int t = 0; t < 9; t++) np += M[t] * M[t];
            float inv2 = __fdividef(1.0f, np);
            float trm = (M[0] + M[4] + M[8]) * (1.0f / 3.0f);

            rp[0 * 16 * RS] = trm * inv2;
            rp[1 * 16 * RS] = 0.5f * (M[1] - M[3]) * inv2;
            rp[2 * 16 * RS] = 0.5f * (M[2] - M[6]) * inv2;
            rp[3 * 16 * RS] = 0.5f * (M[5] - M[7]) * inv2;
            rp[4 * 16 * RS] = (M[0] - trm) * inv2;
            rp[5 * 16 * RS] = 0.5f * (M[1] + M[3]) * inv2;
            rp[6 * 16 * RS] = 0.5f * (M[2] + M[6]) * inv2;
            rp[7 * 16 * RS] = (M[4] - trm) * inv2;
            rp[8 * 16 * RS] = 0.5f * (M[5] + M[7]) * inv2;
        }
        __syncthreads();

        // ---------- GEMM stage 2 (mats 3..5), warp per rt, in-place ----------
        #pragma unroll 1
        for (int rt = wid; rt < 9; rt += 8) {
            int mat = 3 + ((rt == 0) ? 0 : (rt < 4) ? 1 : 2);
            const float* crow0 = cr + (16 * rt + gr) * RS;
            const float* crow1 = crow0 + 8 * RS;
            uint32_t Ah[2][4], Al[2][4];
            #pragma unroll
            for (int kf = 0; kf < 2; kf++) {
                int c0 = kf * 16 + 2 * tig;
                float2 v0 = *(const float2*)(crow0 + c0);
                float2 v1 = *(const float2*)(crow1 + c0);
                float2 v2 = *(const float2*)(crow0 + c0 + 8);
                float2 v3 = *(const float2*)(crow1 + c0 + 8);
                pack_hl(v0.x, v0.y, Ah[kf][0], Al[kf][0]);
                pack_hl(v1.x, v1.y, Ah[kf][1], Al[kf][1]);
                pack_hl(v2.x, v2.y, Ah[kf][2], Al[kf][2]);
                pack_hl(v3.x, v3.y, Ah[kf][3], Al[kf][3]);
            }
            float D[4][4];
            #pragma unroll
            for (int nt = 0; nt < 4; nt++) {
                D[nt][0] = 0.f; D[nt][1] = 0.f; D[nt][2] = 0.f; D[nt][3] = 0.f;
                #pragma unroll
                for (int kf = 0; kf < 2; kf++) {
                    uint2 Bh = sBh[mat * 256 + (nt * 2 + kf) * 32 + lane];
                    uint2 Bl = sBl[mat * 256 + (nt * 2 + kf) * 32 + lane];
                    mma_bf16(D[nt], Ah[kf], Bh);
                    mma_bf16(D[nt], Al[kf], Bh);
                    mma_bf16(D[nt], Ah[kf], Bl);
                }
            }
            float* wr0 = cr + (16 * rt + gr) * RS + 2 * tig;
            float* wr1 = wr0 + 8 * RS;
            #pragma unroll
            for (int nt = 0; nt < 4; nt++) {
                *(float2*)(wr0 + nt * 8) = make_float2(D[nt][0], D[nt][1]);
                *(float2*)(wr1 + nt * 8) = make_float2(D[nt][2], D[nt][3]);
            }
        }
        __syncthreads();

        // ---------- EW-C: D, out = Xn + D + D@D ----------
        #pragma unroll
        for (int cc = 0; cc < 2; cc++) {
            int r0 = nl0 + cc * 8;
            int n  = nodeBase + r0;
            const float* rp = cr + r0 * RS + u;
            float Ip2 = rp[0 * 16 * RS];
            float b01 = rp[1 * 16 * RS];
            float b02 = rp[2 * 16 * RS];
            float b12 = rp[3 * 16 * RS];
            float t00 = rp[4 * 16 * RS];
            float t01 = rp[5 * 16 * RS];
            float t02 = rp[6 * 16 * RS];
            float t11 = rp[7 * 16 * RS];
            float t12 = rp[8 * 16 * RS];
            float t22 = -(t00 + t11);

            float D[9];
            D[0] = Ip2 + t00;  D[1] = b01 + t01;  D[2] = b02 + t02;
            D[3] = t01 - b01;  D[4] = Ip2 + t11;  D[5] = b12 + t12;
            D[6] = t02 - b02;  D[7] = t12 - b12;  D[8] = Ip2 + t22;

            if (n < nNodes) {
                #pragma unroll
                for (int i = 0; i < 3; i++)
                    #pragma unroll
                    for (int l = 0; l < 3; l++) {
                        float o = Xn[cc][i*3+l] + D[i*3+l];
                        #pragma unroll
                        for (int j = 0; j < 3; j++)
                            o += D[i*3+j] * D[j*3+l];
                        out[((size_t)n * 9 + (i*3+l)) * 32 + u] = o;
                    }
            }
        }
        __syncthreads();   // protect cr before next strip
    }
}

// ---------------------------------------------------------------------------
extern "C" void kernel_launch(void* const* d_in, const int* in_sizes, int n_in,
                              void* d_out, int out_size)
{
    const float* X           = (const float*)d_in[0];
    const int*   edge_index  = (const int*)  d_in[1];
    const float* edge_weight = (const float*)d_in[2];
    const float* edge_attr   = (const float*)d_in[3];
    const float* W1 = (const float*)d_in[4];
    const float* b1 = (const float*)d_in[5];
    const float* W2 = (const float*)d_in[6];
    const float* b2 = (const float*)d_in[7];
    const float* W3 = (const float*)d_in[8];
    const float* b3 = (const float*)d_in[9];
    const float* Wt = (const float*)d_in[10];
    float* out = (float*)d_out;

    int N = in_sizes[0] / 288;   // X is (N,3,3,32)
    if (N > MAXN) N = MAXN;
    int E = in_sizes[2];         // edge_weight is (E,)

    int nStrips = (E + 15) >> 4;
    int grid = (nStrips + 7) / 8;
    if (grid > 296) grid = 296;

    edge_mma_kernel<<<grid, 256>>>(
        edge_attr, edge_index, edge_weight, W1, b1, W2, b2, W3, b3, E);

    // Node kernel: dynamic smem = B-frags (24576) + in-place cr buffer.
    int nodeSmem = 24576 + 144 * RS * 4;   // 45312 bytes
    static bool attr_set = false;
    if (!attr_set) {
        cudaFuncSetAttribute(node_mma_kernel,
                             cudaFuncAttributeMaxDynamicSharedMemorySize, nodeSmem);
        attr_set = true;
    }
    int nodeStrips = (N + 15) / 16;
    int nodeGrid = nodeStrips < 592 ? nodeStrips : 592;
    node_mma_kernel<<<nodeGrid, 256, nodeSmem>>>(X, Wt, out, N, nodeStrips);
}